// round 14
// baseline (speedup 1.0000x reference)
#include <cuda_runtime.h>
#include <cuda_fp16.h>
#include <cstdint>

#define DIM 64
#define LMAX 200000
#define CMAX 80000
#define EMAX 1100000
#define SCAN_NB 256

// -------- scratch (static __device__ arrays; no allocation allowed) --------
__device__ float g_Ml2c[(size_t)LMAX * DIM];   // 51.2 MB
__device__ float g_Mc2l[(size_t)CMAX * DIM];   // 20.5 MB
__device__ float g_Ml2l[(size_t)LMAX * DIM];   // 51.2 MB
__device__ float g_aggrC[(size_t)CMAX * DIM];  // 20.5 MB
__device__ float g_aggrL[(size_t)LMAX * DIM];  // 51.2 MB
// CSR scratch
__device__ int g_cntC[CMAX],  g_rowC[CMAX + 1], g_curC[CMAX], g_srcC[EMAX];
__device__ int g_cntL[LMAX],  g_rowL[LMAX + 1], g_curL[LMAX], g_srcL[EMAX];
__device__ int g_bsumC[SCAN_NB], g_bsumL[SCAN_NB];

// ---------------------------------------------------------------------------
__device__ __forceinline__ void mma_16816(float* d, const uint32_t* a,
                                          const uint32_t* b)
{
    asm volatile(
        "mma.sync.aligned.m16n8k16.row.col.f32.f16.f16.f32 "
        "{%0,%1,%2,%3}, {%4,%5,%6,%7}, {%8,%9}, {%0,%1,%2,%3};\n"
        : "+f"(d[0]), "+f"(d[1]), "+f"(d[2]), "+f"(d[3])
        : "r"(a[0]), "r"(a[1]), "r"(a[2]), "r"(a[3]), "r"(b[0]), "r"(b[1]));
}

// ---------------------------------------------------------------------------
__device__ __forceinline__ void init_bias_frag(float a[2][4][4], const float* b,
                                               int wn, int tig)
{
    #pragma unroll
    for (int nt = 0; nt < 4; ++nt) {
        float bv0 = b[wn + nt * 8 + 2 * tig];
        float bv1 = b[wn + nt * 8 + 2 * tig + 1];
        #pragma unroll
        for (int mt = 0; mt < 2; ++mt) {
            a[mt][nt][0] = bv0; a[mt][nt][1] = bv1;
            a[mt][nt][2] = bv0; a[mt][nt][3] = bv1;
        }
    }
}

// acc += A[128 rows x 64 cols, stride 72] @ (Wh+Wl) over one 64-wide K segment
__device__ __forceinline__ void mma_accum_64(
    float acc[2][4][4],
    const __half* __restrict__ A,
    const __half* __restrict__ Wh, const __half* __restrict__ Wl,
    int wstride, int koff,
    int wm, int wn, int gid, int tig)
{
    #pragma unroll
    for (int kb = 0; kb < 4; ++kb) {
        const int k0 = kb * 16;
        uint32_t ah[2][4];
        #pragma unroll
        for (int mt = 0; mt < 2; ++mt) {
            int r0 = (wm + mt * 16 + gid) * 72;
            int r8 = r0 + 8 * 72;
            ah[mt][0] = *(const uint32_t*)(A + r0 + k0 + 2 * tig);
            ah[mt][1] = *(const uint32_t*)(A + r8 + k0 + 2 * tig);
            ah[mt][2] = *(const uint32_t*)(A + r0 + k0 + 2 * tig + 8);
            ah[mt][3] = *(const uint32_t*)(A + r8 + k0 + 2 * tig + 8);
        }
        uint32_t bh[4][2], bl[4][2];
        #pragma unroll
        for (int nt = 0; nt < 4; ++nt) {
            int n = (wn + nt * 8 + gid) * wstride + koff + k0;
            bh[nt][0] = *(const uint32_t*)(Wh + n + 2 * tig);
            bh[nt][1] = *(const uint32_t*)(Wh + n + 2 * tig + 8);
            bl[nt][0] = *(const uint32_t*)(Wl + n + 2 * tig);
            bl[nt][1] = *(const uint32_t*)(Wl + n + 2 * tig + 8);
        }
        #pragma unroll
        for (int nt = 0; nt < 4; ++nt) {
            mma_16816(acc[0][nt], ah[0], bh[nt]);
            mma_16816(acc[1][nt], ah[1], bh[nt]);
        }
        #pragma unroll
        for (int nt = 0; nt < 4; ++nt) {
            mma_16816(acc[0][nt], ah[0], bl[nt]);
            mma_16816(acc[1][nt], ah[1], bl[nt]);
        }
    }
}

__device__ __forceinline__ void relu_to_smem(const float a[2][4][4], __half* Hs,
                                             int wm, int wn, int gid, int tig)
{
    #pragma unroll
    for (int mt = 0; mt < 2; ++mt)
        #pragma unroll
        for (int nt = 0; nt < 4; ++nt) {
            int r0 = wm + mt * 16 + gid;
            int c0 = wn + nt * 8 + 2 * tig;
            *(__half2*)(Hs + r0 * 72 + c0) =
                __floats2half2_rn(fmaxf(a[mt][nt][0], 0.f), fmaxf(a[mt][nt][1], 0.f));
            *(__half2*)(Hs + (r0 + 8) * 72 + c0) =
                __floats2half2_rn(fmaxf(a[mt][nt][2], 0.f), fmaxf(a[mt][nt][3], 0.f));
        }
}

__device__ __forceinline__ void epilogue_store(const float o[2][4][4], float* out,
                                               int base, int nrows, bool flip,
                                               int wm, int wn, int gid, int tig)
{
    #pragma unroll
    for (int mt = 0; mt < 2; ++mt)
        #pragma unroll
        for (int nt = 0; nt < 4; ++nt) {
            int r = base + wm + mt * 16 + gid;
            int c = wn + nt * 8 + 2 * tig;
            if (r < nrows) {
                int ro = flip ? (r ^ 1) : r;
                *(float2*)(out + (size_t)ro * 64 + c) =
                    make_float2(o[mt][nt][0], o[mt][nt][1]);
            }
            if (r + 8 < nrows) {
                int ro = flip ? ((r + 8) ^ 1) : (r + 8);
                *(float2*)(out + (size_t)ro * 64 + c) =
                    make_float2(o[mt][nt][2], o[mt][nt][3]);
            }
        }
}

// ---------------------------------------------------------------------------
// Single MLP: 128-row tiles, 256 threads, register prefetch, and layer-2
// reads the relu result written back into Xs (no separate Hs) -> ~18KB less
// smem -> 3 blocks/SM.
// ---------------------------------------------------------------------------
template <int PARTS>
__global__ __launch_bounds__(256, 3) void mlp_single(
    const float* __restrict__ x0, const float* __restrict__ x1,
    const float* __restrict__ x2,
    const float* __restrict__ W1, const float* __restrict__ b1,
    const float* __restrict__ W2, const float* __restrict__ b2,
    float* __restrict__ out, int nrows)
{
    constexpr int K  = PARTS * 64;
    constexpr int WS = K + 8;

    extern __shared__ __half smh[];
    __half* W1h = smh;                 // [64][WS]
    __half* W1l = W1h + 64 * WS;
    __half* W2h = W1l + 64 * WS;       // [64][72]
    __half* W2l = W2h + 64 * 72;
    __half* Xs  = W2l + 64 * 72;       // [128][72]  X, then relu(H) in place
    float*  bias = (float*)(Xs + 128 * 72);

    const int tid = threadIdx.x;
    for (int i = tid; i < K * 64; i += 256) {
        int k = i >> 6, n = i & 63;
        float w = W1[i];
        __half hi = __float2half_rn(w);
        W1h[n * WS + k] = hi;
        W1l[n * WS + k] = __float2half_rn(w - __half2float(hi));
    }
    for (int i = tid; i < 64 * 64; i += 256) {
        int k = i >> 6, n = i & 63;
        float w = W2[i];
        __half hi = __float2half_rn(w);
        W2h[n * 72 + k] = hi;
        W2l[n * 72 + k] = __float2half_rn(w - __half2float(hi));
    }
    if (tid < 64) { bias[tid] = b1[tid]; bias[64 + tid] = b2[tid]; }
    __syncthreads();   // weights+bias visible to all warps (R3/R4 lesson)

    const int lane = tid & 31;
    const int warp = tid >> 5;
    const int gid = lane >> 2, tig = lane & 3;
    const int wm = (warp & 3) * 32;   // 4 m-quadrants over 128 rows
    const int wn = (warp >> 2) * 32;  // 2 n-quadrants over 64 cols

    const int ntiles = (nrows + 127) >> 7;
    int tile = blockIdx.x;
    float2 pf[16];
    if (tile < ntiles) {
        #pragma unroll
        for (int i = 0; i < 16; ++i) {
            int idx = tid + i * 256;
            int r = idx >> 5, kp = idx & 31;
            int row = (tile << 7) + r;
            pf[i] = (row < nrows) ? *(const float2*)(x0 + (size_t)row * 64 + 2 * kp)
                                  : make_float2(0.f, 0.f);
        }
    }

    for (; tile < ntiles; tile += gridDim.x) {
        const int base = tile << 7;
        float acc[2][4][4];
        init_bias_frag(acc, bias, wn, tig);

        #pragma unroll
        for (int p = 0; p < PARTS; ++p) {
            __syncthreads();   // Xs reusable (prev part / prev tile L2 done)
            #pragma unroll
            for (int i = 0; i < 16; ++i) {
                int idx = tid + i * 256;
                int r = idx >> 5, kp = idx & 31;
                *(__half2*)(Xs + r * 72 + 2 * kp) = __floats2half2_rn(pf[i].x, pf[i].y);
            }
            __syncthreads();
            // prefetch next stage while MMAs run
            int np = p + 1;
            int ntile = tile;
            if (np == PARTS) { np = 0; ntile = tile + (int)gridDim.x; }
            if (ntile < ntiles) {
                const float* nx = (np == 0) ? x0 : ((np == 1) ? x1 : x2);
                int nb = ntile << 7;
                #pragma unroll
                for (int i = 0; i < 16; ++i) {
                    int idx = tid + i * 256;
                    int r = idx >> 5, kp = idx & 31;
                    int row = nb + r;
                    pf[i] = (row < nrows)
                          ? *(const float2*)(nx + (size_t)row * 64 + 2 * kp)
                          : make_float2(0.f, 0.f);
                }
            }
            mma_accum_64(acc, Xs, W1h, W1l, WS, p * 64, wm, wn, gid, tig);
        }

        __syncthreads();                 // all warps done reading Xs (layer 1)
        relu_to_smem(acc, Xs, wm, wn, gid, tig);   // H overwrites Xs
        __syncthreads();                 // H visible
        float o[2][4][4];
        init_bias_frag(o, bias + 64, wn, tig);
        mma_accum_64(o, Xs, W2h, W2l, 72, 0, wm, wn, gid, tig);
        epilogue_store(o, out, base, nrows, false, wm, wn, gid, tig);
        // loop-top sync protects Xs against next tile's staging
    }
}

// ---------------------------------------------------------------------------
// Fused l2c + l2l kernel (R11 shape, validated): both MLPs on the same staged
// X; second output written pair-flipped. Separate Hs (Xs must persist).
// ---------------------------------------------------------------------------
__global__ __launch_bounds__(256, 2) void mlp_fused(
    const float* __restrict__ x0,
    const float* __restrict__ W1a, const float* __restrict__ b1a,
    const float* __restrict__ W2a, const float* __restrict__ b2a,
    float* __restrict__ outA,
    const float* __restrict__ W1b, const float* __restrict__ b1b,
    const float* __restrict__ W2b, const float* __restrict__ b2b,
    float* __restrict__ outB,
    int nrows)
{
    constexpr int WS = 72;

    extern __shared__ __half smh[];
    __half* W1ah = smh;                 // [64][72]
    __half* W1al = W1ah + 64 * 72;
    __half* W2ah = W1al + 64 * 72;
    __half* W2al = W2ah + 64 * 72;
    __half* W1bh = W2al + 64 * 72;
    __half* W1bl = W1bh + 64 * 72;
    __half* W2bh = W1bl + 64 * 72;
    __half* W2bl = W2bh + 64 * 72;
    __half* Xs   = W2bl + 64 * 72;      // [128][72]
    __half* Hs   = Xs + 128 * 72;       // [128][72]
    float*  bias = (float*)(Hs + 128 * 72);

    const int tid = threadIdx.x;
    for (int i = tid; i < 64 * 64; i += 256) {
        int k = i >> 6, n = i & 63;
        float w;
        __half hi;
        w = W1a[i]; hi = __float2half_rn(w);
        W1ah[n * 72 + k] = hi; W1al[n * 72 + k] = __float2half_rn(w - __half2float(hi));
        w = W2a[i]; hi = __float2half_rn(w);
        W2ah[n * 72 + k] = hi; W2al[n * 72 + k] = __float2half_rn(w - __half2float(hi));
        w = W1b[i]; hi = __float2half_rn(w);
        W1bh[n * 72 + k] = hi; W1bl[n * 72 + k] = __float2half_rn(w - __half2float(hi));
        w = W2b[i]; hi = __float2half_rn(w);
        W2bh[n * 72 + k] = hi; W2bl[n * 72 + k] = __float2half_rn(w - __half2float(hi));
    }
    if (tid < 64) {
        bias[tid] = b1a[tid]; bias[64 + tid] = b2a[tid];
        bias[128 + tid] = b1b[tid]; bias[192 + tid] = b2b[tid];
    }
    __syncthreads();

    const int lane = tid & 31;
    const int warp = tid >> 5;
    const int gid = lane >> 2, tig = lane & 3;
    const int wm = (warp & 3) * 32;
    const int wn = (warp >> 2) * 32;

    const int ntiles = (nrows + 127) >> 7;
    int tile = blockIdx.x;
    float2 pf[16];
    if (tile < ntiles) {
        #pragma unroll
        for (int i = 0; i < 16; ++i) {
            int idx = tid + i * 256;
            int r = idx >> 5, kp = idx & 31;
            int row = (tile << 7) + r;
            pf[i] = (row < nrows) ? *(const float2*)(x0 + (size_t)row * 64 + 2 * kp)
                                  : make_float2(0.f, 0.f);
        }
    }

    for (; tile < ntiles; tile += gridDim.x) {
        const int base = tile << 7;
        float acc[2][4][4];
        init_bias_frag(acc, bias, wn, tig);

        __syncthreads();
        #pragma unroll
        for (int i = 0; i < 16; ++i) {
            int idx = tid + i * 256;
            int r = idx >> 5, kp = idx & 31;
            *(__half2*)(Xs + r * 72 + 2 * kp) = __floats2half2_rn(pf[i].x, pf[i].y);
        }
        __syncthreads();
        int ntile = tile + (int)gridDim.x;
        if (ntile < ntiles) {
            int nb = ntile << 7;
            #pragma unroll
            for (int i = 0; i < 16; ++i) {
                int idx = tid + i * 256;
                int r = idx >> 5, kp = idx & 31;
                int row = nb + r;
                pf[i] = (row < nrows)
                      ? *(const float2*)(x0 + (size_t)row * 64 + 2 * kp)
                      : make_float2(0.f, 0.f);
            }
        }
        mma_accum_64(acc, Xs, W1ah, W1al, WS, 0, wm, wn, gid, tig);

        relu_to_smem(acc, Hs, wm, wn, gid, tig);
        __syncthreads();
        float o[2][4][4];
        init_bias_frag(o, bias + 64, wn, tig);
        mma_accum_64(o, Hs, W2ah, W2al, 72, 0, wm, wn, gid, tig);
        epilogue_store(o, outA, base, nrows, false, wm, wn, gid, tig);

        __syncthreads();   // all warps done reading Hs before rewrite
        float acc2[2][4][4];
        init_bias_frag(acc2, bias + 128, wn, tig);
        mma_accum_64(acc2, Xs, W1bh, W1bl, 72, 0, wm, wn, gid, tig);
        relu_to_smem(acc2, Hs, wm, wn, gid, tig);
        __syncthreads();
        float o2[2][4][4];
        init_bias_frag(o2, bias + 192, wn, tig);
        mma_accum_64(o2, Hs, W2bh, W2bl, 72, 0, wm, wn, gid, tig);
        epilogue_store(o2, outB, base, nrows, true, wm, wn, gid, tig);
    }
}

// ---------------------------------------------------------------------------
// CSR build: fused count (both CSRs per edge pass) -> scans -> fused place
// ---------------------------------------------------------------------------
__global__ void count2_kernel(const int* __restrict__ ce, const int* __restrict__ le,
                              int E, int* __restrict__ cntC, int* __restrict__ cntL)
{
    int e = blockIdx.x * 256 + threadIdx.x;
    if (e < E) {
        atomicAdd(&cntC[ce[e]], 1);
        atomicAdd(&cntL[le[e]], 1);
    }
}

__global__ void scan_reduce(const int* __restrict__ cnt, int n, int* __restrict__ bsum)
{
    int b = blockIdx.x;
    int CH = (n + SCAN_NB - 1) / SCAN_NB;
    int s = b * CH, e = min(n, s + CH);
    __shared__ int sh[256];
    int t = threadIdx.x, sum = 0;
    for (int i = s + t; i < e; i += 256) sum += cnt[i];
    sh[t] = sum; __syncthreads();
    for (int o = 128; o > 0; o >>= 1) {
        if (t < o) sh[t] += sh[t + o];
        __syncthreads();
    }
    if (t == 0) bsum[b] = sh[0];
}

__global__ void scan_bsum(int* __restrict__ bsum)
{
    __shared__ int sh[256];
    int t = threadIdx.x;
    sh[t] = bsum[t]; __syncthreads();
    for (int o = 1; o < 256; o <<= 1) {
        int v = (t >= o) ? sh[t - o] : 0;
        __syncthreads();
        sh[t] += v;
        __syncthreads();
    }
    bsum[t] = (t == 0) ? 0 : sh[t - 1];
}

__global__ void scan_write(const int* __restrict__ cnt, int n,
                           const int* __restrict__ bsum, int* __restrict__ rowptr, int total)
{
    int b = blockIdx.x;
    int CH = (n + SCAN_NB - 1) / SCAN_NB;
    int s = b * CH, e = min(n, s + CH);
    int t = threadIdx.x;
    int per = (CH + 255) / 256;
    int ts = min(e, s + t * per), te = min(e, s + t * per + per);
    int sum = 0;
    for (int i = ts; i < te; ++i) sum += cnt[i];
    __shared__ int sh[256];
    sh[t] = sum; __syncthreads();
    for (int o = 1; o < 256; o <<= 1) {
        int v = (t >= o) ? sh[t - o] : 0;
        __syncthreads();
        sh[t] += v;
        __syncthreads();
    }
    int off = bsum[b] + ((t == 0) ? 0 : sh[t - 1]);
    for (int i = ts; i < te; ++i) { rowptr[i] = off; off += cnt[i]; }
    if (b == 0 && t == 0) rowptr[n] = total;
}

__global__ void place2_kernel(const int* __restrict__ ce, const int* __restrict__ le,
                              int E, int* __restrict__ curC, int* __restrict__ srcC,
                              int* __restrict__ curL, int* __restrict__ srcL)
{
    int e = blockIdx.x * 256 + threadIdx.x;
    if (e < E) {
        int c = ce[e], l = le[e];
        srcC[atomicAdd(&curC[c], 1)] = l;
        srcL[atomicAdd(&curL[l], 1)] = c;
    }
}

// ---------------------------------------------------------------------------
// Gather aggregation (R11-validated): 16 lanes/dest, float4 per lane.
// ---------------------------------------------------------------------------
__global__ __launch_bounds__(256) void gather_kernel(
    const float* __restrict__ src, const int* __restrict__ srcidx,
    const int* __restrict__ rowptr, float* __restrict__ dst, int n)
{
    int d = blockIdx.x * 16 + (threadIdx.x >> 4);
    int q = threadIdx.x & 15;
    if (d >= n) return;
    int s = rowptr[d], e = rowptr[d + 1];
    float ax = 0.f, ay = 0.f, az = 0.f, aw = 0.f;
    for (int i = s; i < e; ++i) {
        int r = __ldg(srcidx + i);
        float4 v = *(const float4*)(src + (size_t)r * 64 + q * 4);
        ax += v.x; ay += v.y; az += v.z; aw += v.w;
    }
    *(float4*)(dst + (size_t)d * 64 + q * 4) = make_float4(ax, ay, az, aw);
}

// ---------------------------------------------------------------------------
static inline size_t mlp_single_smem(int parts)
{
    size_t WS = parts * 64 + 8;
    size_t halves = 2 * 64 * WS + 2 * 64 * 72 + (size_t)128 * 72;
    return halves * 2 + 128 * sizeof(float);
}
static inline size_t mlp_fused_smem()
{
    size_t halves = (size_t)8 * 64 * 72 + (size_t)2 * 128 * 72;
    return halves * 2 + 256 * sizeof(float);
}

extern "C" void kernel_launch(void* const* d_in, const int* in_sizes, int n_in,
                              void* d_out, int out_size)
{
    const int off = n_in - 24;
    const int* l_edge = (const int*)d_in[off + 0];
    const int* c_edge = (const int*)d_in[off + 1];
    const float* l_emb_in = (const float*)d_in[off + 2];
    const float* c_emb_in = (const float*)d_in[off + 3];
    const int E = in_sizes[off + 0];
    const int L = in_sizes[off + 2] / DIM;
    const int C = in_sizes[off + 3] / DIM;

    const float* W[5][4];
    for (int m = 0; m < 5; ++m)
        for (int j = 0; j < 4; ++j)
            W[m][j] = (const float*)d_in[off + 4 + m * 4 + j];
    // m: 0=l2c, 1=c2l, 2=l2l, 3=cu, 4=lu

    float* Ml2c, * Mc2l, * Ml2l, * aggrC, * aggrL;
    int *cntC, *rowC, *curC, *srcC, *bsC;
    int *cntL, *rowL, *curL, *srcL, *bsL;
    cudaGetSymbolAddress((void**)&Ml2c, g_Ml2c);
    cudaGetSymbolAddress((void**)&Mc2l, g_Mc2l);
    cudaGetSymbolAddress((void**)&Ml2l, g_Ml2l);
    cudaGetSymbolAddress((void**)&aggrC, g_aggrC);
    cudaGetSymbolAddress((void**)&aggrL, g_aggrL);
    cudaGetSymbolAddress((void**)&cntC, g_cntC);
    cudaGetSymbolAddress((void**)&rowC, g_rowC);
    cudaGetSymbolAddress((void**)&curC, g_curC);
    cudaGetSymbolAddress((void**)&srcC, g_srcC);
    cudaGetSymbolAddress((void**)&bsC,  g_bsumC);
    cudaGetSymbolAddress((void**)&cntL, g_cntL);
    cudaGetSymbolAddress((void**)&rowL, g_rowL);
    cudaGetSymbolAddress((void**)&curL, g_curL);
    cudaGetSymbolAddress((void**)&srcL, g_srcL);
    cudaGetSymbolAddress((void**)&bsL,  g_bsumL);

    const size_t smF = mlp_fused_smem();
    const size_t sm1 = mlp_single_smem(1);
    const size_t sm2 = mlp_single_smem(2);
    const size_t sm3 = mlp_single_smem(3);
    cudaFuncSetAttribute(mlp_fused,     cudaFuncAttributeMaxDynamicSharedMemorySize, (int)smF);
    cudaFuncSetAttribute(mlp_single<1>, cudaFuncAttributeMaxDynamicSharedMemorySize, (int)sm1);
    cudaFuncSetAttribute(mlp_single<2>, cudaFuncAttributeMaxDynamicSharedMemorySize, (int)sm2);
    cudaFuncSetAttribute(mlp_single<3>, cudaFuncAttributeMaxDynamicSharedMemorySize, (int)sm3);

    float* outBase = (float*)d_out;
    float* outL = outBase;                          // (3, L, 64)
    float* outC = outBase + (size_t)3 * L * DIM;    // (3, C, 64)

    cudaMemcpyAsync(outL, l_emb_in, (size_t)L * DIM * sizeof(float), cudaMemcpyDeviceToDevice);
    cudaMemcpyAsync(outC, c_emb_in, (size_t)C * DIM * sizeof(float), cudaMemcpyDeviceToDevice);

    // ---- CSR build (fused per-edge passes) ----
    const int eb = (E + 255) / 256;
    cudaMemsetAsync(cntC, 0, C * sizeof(int));
    cudaMemsetAsync(cntL, 0, L * sizeof(int));
    count2_kernel<<<eb, 256>>>(c_edge, l_edge, E, cntC, cntL);
    scan_reduce<<<SCAN_NB, 256>>>(cntC, C, bsC);
    scan_reduce<<<SCAN_NB, 256>>>(cntL, L, bsL);
    scan_bsum<<<1, 256>>>(bsC);
    scan_bsum<<<1, 256>>>(bsL);
    scan_write<<<SCAN_NB, 256>>>(cntC, C, bsC, rowC, E);
    scan_write<<<SCAN_NB, 256>>>(cntL, L, bsL, rowL, E);
    cudaMemcpyAsync(curC, rowC, C * sizeof(int), cudaMemcpyDeviceToDevice);
    cudaMemcpyAsync(curL, rowL, L * sizeof(int), cudaMemcpyDeviceToDevice);
    place2_kernel<<<eb, 256>>>(c_edge, l_edge, E, curC, srcC, curL, srcL);

    const int ltiles = (L + 127) >> 7;
    const int ctiles = (C + 127) >> 7;
    auto gridFor = [](int tiles, int maxResident) {
        return tiles < maxResident ? tiles : maxResident;
    };
    const int gF  = gridFor(ltiles, 148 * 2);
    const int g1C = gridFor(ctiles, 148 * 3);
    const int g2C = gridFor(ctiles, 148 * 3);
    const int g3L = gridFor(ltiles, 148 * 2);

    for (int t = 0; t < 2; ++t) {
        const float* le = outL + (size_t)t * L * DIM;
        const float* ce = outC + (size_t)t * C * DIM;
        float* nle = outL + (size_t)(t + 1) * L * DIM;
        float* nce = outC + (size_t)(t + 1) * C * DIM;

        // fused messages from le: l2c (plain) + l2l (flipped output)
        mlp_fused<<<gF, 256, smF>>>(le,
            W[0][0], W[0][1], W[0][2], W[0][3], Ml2c,
            W[2][0], W[2][1], W[2][2], W[2][3], Ml2l, L);
        // c2l from ce
        mlp_single<1><<<g1C, 256, sm1>>>(ce, nullptr, nullptr,
            W[1][0], W[1][1], W[1][2], W[1][3], Mc2l, C);

        // aggregation via gather (no atomics, no memsets)
        gather_kernel<<<(C + 15) / 16, 256>>>(Ml2c, srcC, rowC, aggrC, C);
        gather_kernel<<<(L + 15) / 16, 256>>>(Mc2l, srcL, rowL, aggrL, L);

        // updates
        mlp_single<2><<<g2C, 256, sm2>>>(ce, aggrC, nullptr,
            W[3][0], W[3][1], W[3][2], W[3][3], nce, C);
        mlp_single<3><<<g3L, 256, sm3>>>(le, aggrL, Ml2l,
            W[4][0], W[4][1], W[4][2], W[4][3], nle, L);
    }
    (void)out_size;
}

// round 15
// speedup vs baseline: 1.0206x; 1.0206x over previous
#include <cuda_runtime.h>
#include <cuda_fp16.h>
#include <cstdint>

#define DIM 64
#define LMAX 200000
#define CMAX 80000
#define EMAX 1100000
#define SCAN_NB 256

// -------- scratch (static __device__ arrays; no allocation allowed) --------
__device__ float g_Ml2c[(size_t)LMAX * DIM];   // 51.2 MB
__device__ float g_Mc2l[(size_t)CMAX * DIM];   // 20.5 MB
__device__ float g_Ml2l[(size_t)LMAX * DIM];   // 51.2 MB
__device__ float g_aggrC[(size_t)CMAX * DIM];  // 20.5 MB
__device__ float g_aggrL[(size_t)LMAX * DIM];  // 51.2 MB
// CSR scratch
__device__ int g_cntC[CMAX],  g_rowC[CMAX + 1], g_curC[CMAX], g_srcC[EMAX];
__device__ int g_cntL[LMAX],  g_rowL[LMAX + 1], g_curL[LMAX], g_srcL[EMAX];
__device__ int g_bsumC[SCAN_NB], g_bsumL[SCAN_NB];

// ---------------------------------------------------------------------------
__device__ __forceinline__ void mma_16816(float* d, const uint32_t* a,
                                          const uint32_t* b)
{
    asm volatile(
        "mma.sync.aligned.m16n8k16.row.col.f32.f16.f16.f32 "
        "{%0,%1,%2,%3}, {%4,%5,%6,%7}, {%8,%9}, {%0,%1,%2,%3};\n"
        : "+f"(d[0]), "+f"(d[1]), "+f"(d[2]), "+f"(d[3])
        : "r"(a[0]), "r"(a[1]), "r"(a[2]), "r"(a[3]), "r"(b[0]), "r"(b[1]));
}

// ---------------------------------------------------------------------------
__device__ __forceinline__ void init_bias_frag(float a[2][4][4], const float* b,
                                               int wn, int tig)
{
    #pragma unroll
    for (int nt = 0; nt < 4; ++nt) {
        float bv0 = b[wn + nt * 8 + 2 * tig];
        float bv1 = b[wn + nt * 8 + 2 * tig + 1];
        #pragma unroll
        for (int mt = 0; mt < 2; ++mt) {
            a[mt][nt][0] = bv0; a[mt][nt][1] = bv1;
            a[mt][nt][2] = bv0; a[mt][nt][3] = bv1;
        }
    }
}

// acc += A[128x64 tile rows] @ (Wh+Wl)  over one 64-wide K segment
__device__ __forceinline__ void mma_accum_64(
    float acc[2][4][4],
    const __half* __restrict__ A,      // [128][72] halves
    const __half* __restrict__ Wh, const __half* __restrict__ Wl,
    int wstride, int koff,
    int wm, int wn, int gid, int tig)
{
    #pragma unroll
    for (int kb = 0; kb < 4; ++kb) {
        const int k0 = kb * 16;
        uint32_t ah[2][4];
        #pragma unroll
        for (int mt = 0; mt < 2; ++mt) {
            int r0 = (wm + mt * 16 + gid) * 72;
            int r8 = r0 + 8 * 72;
            ah[mt][0] = *(const uint32_t*)(A + r0 + k0 + 2 * tig);
            ah[mt][1] = *(const uint32_t*)(A + r8 + k0 + 2 * tig);
            ah[mt][2] = *(const uint32_t*)(A + r0 + k0 + 2 * tig + 8);
            ah[mt][3] = *(const uint32_t*)(A + r8 + k0 + 2 * tig + 8);
        }
        uint32_t bh[4][2], bl[4][2];
        #pragma unroll
        for (int nt = 0; nt < 4; ++nt) {
            int n = (wn + nt * 8 + gid) * wstride + koff + k0;
            bh[nt][0] = *(const uint32_t*)(Wh + n + 2 * tig);
            bh[nt][1] = *(const uint32_t*)(Wh + n + 2 * tig + 8);
            bl[nt][0] = *(const uint32_t*)(Wl + n + 2 * tig);
            bl[nt][1] = *(const uint32_t*)(Wl + n + 2 * tig + 8);
        }
        #pragma unroll
        for (int nt = 0; nt < 4; ++nt) {
            mma_16816(acc[0][nt], ah[0], bh[nt]);
            mma_16816(acc[1][nt], ah[1], bh[nt]);
        }
        #pragma unroll
        for (int nt = 0; nt < 4; ++nt) {
            mma_16816(acc[0][nt], ah[0], bl[nt]);
            mma_16816(acc[1][nt], ah[1], bl[nt]);
        }
    }
}

__device__ __forceinline__ void relu_to_smem(const float a[2][4][4], __half* Hs,
                                             int wm, int wn, int gid, int tig)
{
    #pragma unroll
    for (int mt = 0; mt < 2; ++mt)
        #pragma unroll
        for (int nt = 0; nt < 4; ++nt) {
            int r0 = wm + mt * 16 + gid;
            int c0 = wn + nt * 8 + 2 * tig;
            *(__half2*)(Hs + r0 * 72 + c0) =
                __floats2half2_rn(fmaxf(a[mt][nt][0], 0.f), fmaxf(a[mt][nt][1], 0.f));
            *(__half2*)(Hs + (r0 + 8) * 72 + c0) =
                __floats2half2_rn(fmaxf(a[mt][nt][2], 0.f), fmaxf(a[mt][nt][3], 0.f));
        }
}

__device__ __forceinline__ void epilogue_store(const float o[2][4][4], float* out,
                                               int base, int nrows, bool flip,
                                               int wm, int wn, int gid, int tig)
{
    #pragma unroll
    for (int mt = 0; mt < 2; ++mt)
        #pragma unroll
        for (int nt = 0; nt < 4; ++nt) {
            int r = base + wm + mt * 16 + gid;
            int c = wn + nt * 8 + 2 * tig;
            if (r < nrows) {
                int ro = flip ? (r ^ 1) : r;
                *(float2*)(out + (size_t)ro * 64 + c) =
                    make_float2(o[mt][nt][0], o[mt][nt][1]);
            }
            if (r + 8 < nrows) {
                int ro = flip ? ((r + 8) ^ 1) : (r + 8);
                *(float2*)(out + (size_t)ro * 64 + c) =
                    make_float2(o[mt][nt][2], o[mt][nt][3]);
            }
        }
}

// ---------------------------------------------------------------------------
// 2-term fp16-split MLP, 128-row tiles, 256 threads, register-prefetch.
// EXACT R11 kernel (validated 624.7us / rel_err 1.233e-4): (256,2), separate Hs.
// FUSE: second MLP (weights b) on the same staged X, output pair-flipped.
// ---------------------------------------------------------------------------
template <int PARTS, bool FUSE>
__global__ __launch_bounds__(256, 2) void mlp_tc(
    const float* __restrict__ x0, const float* __restrict__ x1,
    const float* __restrict__ x2,
    const float* __restrict__ W1a, const float* __restrict__ b1a,
    const float* __restrict__ W2a, const float* __restrict__ b2a,
    float* __restrict__ outA,
    const float* __restrict__ W1b, const float* __restrict__ b1b,
    const float* __restrict__ W2b, const float* __restrict__ b2b,
    float* __restrict__ outB,
    int nrows)
{
    constexpr int K  = PARTS * 64;
    constexpr int WS = K + 8;

    extern __shared__ __half smh[];
    __half* W1ah = smh;                       // [64][WS]
    __half* W1al = W1ah + 64 * WS;
    __half* W2ah = W1al + 64 * WS;            // [64][72]
    __half* W2al = W2ah + 64 * 72;
    __half* W1bh = W2al + 64 * 72;            // FUSE only (K=64, stride 72)
    __half* W1bl = W1bh + (FUSE ? 64 * 72 : 0);
    __half* W2bh = W1bl + (FUSE ? 64 * 72 : 0);
    __half* W2bl = W2bh + (FUSE ? 64 * 72 : 0);
    __half* Xs   = W2bl + (FUSE ? 64 * 72 : 0);   // [128][72]
    __half* Hs   = Xs + 128 * 72;                 // [128][72]
    float*  bias = (float*)(Hs + 128 * 72);       // b1a,b2a[,b1b,b2b] x64

    const int tid = threadIdx.x;
    for (int i = tid; i < K * 64; i += 256) {
        int k = i >> 6, n = i & 63;
        float w = W1a[i];
        __half hi = __float2half_rn(w);
        W1ah[n * WS + k] = hi;
        W1al[n * WS + k] = __float2half_rn(w - __half2float(hi));
    }
    for (int i = tid; i < 64 * 64; i += 256) {
        int k = i >> 6, n = i & 63;
        float w = W2a[i];
        __half hi = __float2half_rn(w);
        W2ah[n * 72 + k] = hi;
        W2al[n * 72 + k] = __float2half_rn(w - __half2float(hi));
    }
    if (FUSE) {
        for (int i = tid; i < 64 * 64; i += 256) {
            int k = i >> 6, n = i & 63;
            float w = W1b[i];
            __half hi = __float2half_rn(w);
            W1bh[n * 72 + k] = hi;
            W1bl[n * 72 + k] = __float2half_rn(w - __half2float(hi));
            float w2 = W2b[i];
            __half h2 = __float2half_rn(w2);
            W2bh[n * 72 + k] = h2;
            W2bl[n * 72 + k] = __float2half_rn(w2 - __half2float(h2));
        }
    }
    if (tid < 64) {
        bias[tid] = b1a[tid]; bias[64 + tid] = b2a[tid];
        if (FUSE) { bias[128 + tid] = b1b[tid]; bias[192 + tid] = b2b[tid]; }
    }
    __syncthreads();   // weights+bias visible to all warps (R3/R4 lesson)

    const int lane = tid & 31;
    const int warp = tid >> 5;
    const int gid = lane >> 2, tig = lane & 3;
    const int wm = (warp & 3) * 32;   // 4 m-quadrants over 128 rows
    const int wn = (warp >> 2) * 32;  // 2 n-quadrants over 64 cols

    const int ntiles = (nrows + 127) >> 7;
    int tile = blockIdx.x;
    float2 pf[16];
    if (tile < ntiles) {   // prologue prefetch: (tile, part 0)
        #pragma unroll
        for (int i = 0; i < 16; ++i) {
            int idx = tid + i * 256;
            int r = idx >> 5, kp = idx & 31;
            int row = (tile << 7) + r;
            pf[i] = (row < nrows) ? *(const float2*)(x0 + (size_t)row * 64 + 2 * kp)
                                  : make_float2(0.f, 0.f);
        }
    }

    for (; tile < ntiles; tile += gridDim.x) {
        const int base = tile << 7;
        float acc[2][4][4];
        init_bias_frag(acc, bias, wn, tig);

        #pragma unroll
        for (int p = 0; p < PARTS; ++p) {
            __syncthreads();   // Xs (and Hs via barrier transitivity) reusable
            #pragma unroll
            for (int i = 0; i < 16; ++i) {
                int idx = tid + i * 256;
                int r = idx >> 5, kp = idx & 31;
                *(__half2*)(Xs + r * 72 + 2 * kp) = __floats2half2_rn(pf[i].x, pf[i].y);
            }
            __syncthreads();
            // prefetch next stage while MMAs run (hides gmem latency)
            int np = p + 1;
            int ntile = tile;
            if (np == PARTS) { np = 0; ntile = tile + (int)gridDim.x; }
            if (ntile < ntiles) {
                const float* nx = (np == 0) ? x0 : ((np == 1) ? x1 : x2);
                int nb = ntile << 7;
                #pragma unroll
                for (int i = 0; i < 16; ++i) {
                    int idx = tid + i * 256;
                    int r = idx >> 5, kp = idx & 31;
                    int row = nb + r;
                    pf[i] = (row < nrows)
                          ? *(const float2*)(nx + (size_t)row * 64 + 2 * kp)
                          : make_float2(0.f, 0.f);
                }
            }
            mma_accum_64(acc, Xs, W1ah, W1al, WS, p * 64, wm, wn, gid, tig);
        }

        relu_to_smem(acc, Hs, wm, wn, gid, tig);
        __syncthreads();
        float o[2][4][4];
        init_bias_frag(o, bias + 64, wn, tig);
        mma_accum_64(o, Hs, W2ah, W2al, 72, 0, wm, wn, gid, tig);
        epilogue_store(o, outA, base, nrows, false, wm, wn, gid, tig);

        if (FUSE) {
            __syncthreads();   // all warps done reading Hs before it is rewritten
            float acc2[2][4][4];
            init_bias_frag(acc2, bias + 128, wn, tig);
            mma_accum_64(acc2, Xs, W1bh, W1bl, 72, 0, wm, wn, gid, tig);
            relu_to_smem(acc2, Hs, wm, wn, gid, tig);
            __syncthreads();
            float o2[2][4][4];
            init_bias_frag(o2, bias + 192, wn, tig);
            mma_accum_64(o2, Hs, W2bh, W2bl, 72, 0, wm, wn, gid, tig);
            epilogue_store(o2, outB, base, nrows, true, wm, wn, gid, tig);
        }
    }
}

// ---------------------------------------------------------------------------
// CSR build: fused count (both CSRs per edge pass) -> scans -> fused place
// ---------------------------------------------------------------------------
__global__ void count2_kernel(const int* __restrict__ ce, const int* __restrict__ le,
                              int E, int* __restrict__ cntC, int* __restrict__ cntL)
{
    int e = blockIdx.x * 256 + threadIdx.x;
    if (e < E) {
        atomicAdd(&cntC[ce[e]], 1);
        atomicAdd(&cntL[le[e]], 1);
    }
}

__global__ void scan_reduce(const int* __restrict__ cnt, int n, int* __restrict__ bsum)
{
    int b = blockIdx.x;
    int CH = (n + SCAN_NB - 1) / SCAN_NB;
    int s = b * CH, e = min(n, s + CH);
    __shared__ int sh[256];
    int t = threadIdx.x, sum = 0;
    for (int i = s + t; i < e; i += 256) sum += cnt[i];
    sh[t] = sum; __syncthreads();
    for (int o = 128; o > 0; o >>= 1) {
        if (t < o) sh[t] += sh[t + o];
        __syncthreads();
    }
    if (t == 0) bsum[b] = sh[0];
}

__global__ void scan_bsum(int* __restrict__ bsum)
{
    __shared__ int sh[256];
    int t = threadIdx.x;
    sh[t] = bsum[t]; __syncthreads();
    for (int o = 1; o < 256; o <<= 1) {
        int v = (t >= o) ? sh[t - o] : 0;
        __syncthreads();
        sh[t] += v;
        __syncthreads();
    }
    bsum[t] = (t == 0) ? 0 : sh[t - 1];
}

__global__ void scan_write(const int* __restrict__ cnt, int n,
                           const int* __restrict__ bsum, int* __restrict__ rowptr, int total)
{
    int b = blockIdx.x;
    int CH = (n + SCAN_NB - 1) / SCAN_NB;
    int s = b * CH, e = min(n, s + CH);
    int t = threadIdx.x;
    int per = (CH + 255) / 256;
    int ts = min(e, s + t * per), te = min(e, s + t * per + per);
    int sum = 0;
    for (int i = ts; i < te; ++i) sum += cnt[i];
    __shared__ int sh[256];
    sh[t] = sum; __syncthreads();
    for (int o = 1; o < 256; o <<= 1) {
        int v = (t >= o) ? sh[t - o] : 0;
        __syncthreads();
        sh[t] += v;
        __syncthreads();
    }
    int off = bsum[b] + ((t == 0) ? 0 : sh[t - 1]);
    for (int i = ts; i < te; ++i) { rowptr[i] = off; off += cnt[i]; }
    if (b == 0 && t == 0) rowptr[n] = total;
}

__global__ void place2_kernel(const int* __restrict__ ce, const int* __restrict__ le,
                              int E, int* __restrict__ curC, int* __restrict__ srcC,
                              int* __restrict__ curL, int* __restrict__ srcL)
{
    int e = blockIdx.x * 256 + threadIdx.x;
    if (e < E) {
        int c = ce[e], l = le[e];
        srcC[atomicAdd(&curC[c], 1)] = l;
        srcL[atomicAdd(&curL[l], 1)] = c;
    }
}

// ---------------------------------------------------------------------------
// Gather aggregation v2: ONE WARP per destination, 2-way edge parallelism.
// Lanes split into parity halves (p = lane>>4); each half walks alternate
// edges with the next srcidx prefetched one step ahead, so the per-edge
// dependent chain is data-load only (~L2 lat) instead of idx->data (2x).
// Halves merged by shfl_xor(16). fp32 end-to-end (R13: fp16 scratch regressed).
// ---------------------------------------------------------------------------
__global__ __launch_bounds__(256) void gather_kernel(
    const float* __restrict__ src, const int* __restrict__ srcidx,
    const int* __restrict__ rowptr, float* __restrict__ dst, int n)
{
    int d = blockIdx.x * 8 + (threadIdx.x >> 5);
    if (d >= n) return;
    const int lane = threadIdx.x & 31;
    const int q = lane & 15;   // float4 column
    const int p = lane >> 4;   // edge parity
    int s = rowptr[d], e = rowptr[d + 1];
    float ax = 0.f, ay = 0.f, az = 0.f, aw = 0.f;
    int i = s + p;
    int r = (i < e) ? __ldg(srcidx + i) : 0;
    while (i < e) {
        int rn = (i + 2 < e) ? __ldg(srcidx + i + 2) : 0;
        float4 v = *(const float4*)(src + (size_t)r * 64 + q * 4);
        ax += v.x; ay += v.y; az += v.z; aw += v.w;
        r = rn;
        i += 2;
    }
    ax += __shfl_xor_sync(0xffffffffu, ax, 16);
    ay += __shfl_xor_sync(0xffffffffu, ay, 16);
    az += __shfl_xor_sync(0xffffffffu, az, 16);
    aw += __shfl_xor_sync(0xffffffffu, aw, 16);
    if (p == 0)
        *(float4*)(dst + (size_t)d * 64 + q * 4) = make_float4(ax, ay, az, aw);
}

// ---------------------------------------------------------------------------
static inline size_t mlp_smem_bytes(int parts, bool fuse)
{
    size_t WS = parts * 64 + 8;
    size_t halves = 2 * 64 * WS + 2 * 64 * 72 + (fuse ? 4 * 64 * 72 : 0)
                  + (size_t)2 * 128 * 72;
    return halves * 2 + 256 * sizeof(float);
}

extern "C" void kernel_launch(void* const* d_in, const int* in_sizes, int n_in,
                              void* d_out, int out_size)
{
    const int off = n_in - 24;
    const int* l_edge = (const int*)d_in[off + 0];
    const int* c_edge = (const int*)d_in[off + 1];
    const float* l_emb_in = (const float*)d_in[off + 2];
    const float* c_emb_in = (const float*)d_in[off + 3];
    const int E = in_sizes[off + 0];
    const int L = in_sizes[off + 2] / DIM;
    const int C = in_sizes[off + 3] / DIM;

    const float* W[5][4];
    for (int m = 0; m < 5; ++m)
        for (int j = 0; j < 4; ++j)
            W[m][j] = (const float*)d_in[off + 4 + m * 4 + j];
    // m: 0=l2c, 1=c2l, 2=l2l, 3=cu, 4=lu

    float* Ml2c, * Mc2l, * Ml2l, * aggrC, * aggrL;
    int *cntC, *rowC, *curC, *srcC, *bsC;
    int *cntL, *rowL, *curL, *srcL, *bsL;
    cudaGetSymbolAddress((void**)&Ml2c, g_Ml2c);
    cudaGetSymbolAddress((void**)&Mc2l, g_Mc2l);
    cudaGetSymbolAddress((void**)&Ml2l, g_Ml2l);
    cudaGetSymbolAddress((void**)&aggrC, g_aggrC);
    cudaGetSymbolAddress((void**)&aggrL, g_aggrL);
    cudaGetSymbolAddress((void**)&cntC, g_cntC);
    cudaGetSymbolAddress((void**)&rowC, g_rowC);
    cudaGetSymbolAddress((void**)&curC, g_curC);
    cudaGetSymbolAddress((void**)&srcC, g_srcC);
    cudaGetSymbolAddress((void**)&bsC,  g_bsumC);
    cudaGetSymbolAddress((void**)&cntL, g_cntL);
    cudaGetSymbolAddress((void**)&rowL, g_rowL);
    cudaGetSymbolAddress((void**)&curL, g_curL);
    cudaGetSymbolAddress((void**)&srcL, g_srcL);
    cudaGetSymbolAddress((void**)&bsL,  g_bsumL);

    const size_t smF = mlp_smem_bytes(1, true);
    const size_t sm1 = mlp_smem_bytes(1, false);
    const size_t sm2 = mlp_smem_bytes(2, false);
    const size_t sm3 = mlp_smem_bytes(3, false);
    cudaFuncSetAttribute(mlp_tc<1, true>,  cudaFuncAttributeMaxDynamicSharedMemorySize, (int)smF);
    cudaFuncSetAttribute(mlp_tc<1, false>, cudaFuncAttributeMaxDynamicSharedMemorySize, (int)sm1);
    cudaFuncSetAttribute(mlp_tc<2, false>, cudaFuncAttributeMaxDynamicSharedMemorySize, (int)sm2);
    cudaFuncSetAttribute(mlp_tc<3, false>, cudaFuncAttributeMaxDynamicSharedMemorySize, (int)sm3);

    float* outBase = (float*)d_out;
    float* outL = outBase;                          // (3, L, 64)
    float* outC = outBase + (size_t)3 * L * DIM;    // (3, C, 64)

    cudaMemcpyAsync(outL, l_emb_in, (size_t)L * DIM * sizeof(float), cudaMemcpyDeviceToDevice);
    cudaMemcpyAsync(outC, c_emb_in, (size_t)C * DIM * sizeof(float), cudaMemcpyDeviceToDevice);

    // ---- CSR build (fused per-edge passes) ----
    const int eb = (E + 255) / 256;
    cudaMemsetAsync(cntC, 0, C * sizeof(int));
    cudaMemsetAsync(cntL, 0, L * sizeof(int));
    count2_kernel<<<eb, 256>>>(c_edge, l_edge, E, cntC, cntL);
    scan_reduce<<<SCAN_NB, 256>>>(cntC, C, bsC);
    scan_reduce<<<SCAN_NB, 256>>>(cntL, L, bsL);
    scan_bsum<<<1, 256>>>(bsC);
    scan_bsum<<<1, 256>>>(bsL);
    scan_write<<<SCAN_NB, 256>>>(cntC, C, bsC, rowC, E);
    scan_write<<<SCAN_NB, 256>>>(cntL, L, bsL, rowL, E);
    cudaMemcpyAsync(curC, rowC, C * sizeof(int), cudaMemcpyDeviceToDevice);
    cudaMemcpyAsync(curL, rowL, L * sizeof(int), cudaMemcpyDeviceToDevice);
    place2_kernel<<<eb, 256>>>(c_edge, l_edge, E, curC, srcC, curL, srcL);

    const int ltiles = (L + 127) >> 7;
    const int ctiles = (C + 127) >> 7;
    auto gridFor = [](int tiles, int maxResident) {
        return tiles < maxResident ? tiles : maxResident;
    };
    const int gF  = gridFor(ltiles, 148 * 2);
    const int g1C = gridFor(ctiles, 148 * 2);
    const int g2C = gridFor(ctiles, 148 * 2);
    const int g3L = gridFor(ltiles, 148 * 2);

    for (int t = 0; t < 2; ++t) {
        const float* le = outL + (size_t)t * L * DIM;
        const float* ce = outC + (size_t)t * C * DIM;
        float* nle = outL + (size_t)(t + 1) * L * DIM;
        float* nce = outC + (size_t)(t + 1) * C * DIM;

        // fused messages from le: l2c (plain) + l2l (flipped output)
        mlp_tc<1, true><<<gF, 256, smF>>>(le, nullptr, nullptr,
            W[0][0], W[0][1], W[0][2], W[0][3], Ml2c,
            W[2][0], W[2][1], W[2][2], W[2][3], Ml2l, L);
        // c2l from ce
        mlp_tc<1, false><<<g1C, 256, sm1>>>(ce, nullptr, nullptr,
            W[1][0], W[1][1], W[1][2], W[1][3], Mc2l,
            nullptr, nullptr, nullptr, nullptr, nullptr, C);

        // aggregation via warp-per-dest gather (2-way edge parallel + prefetch)
        gather_kernel<<<(C + 7) / 8, 256>>>(Ml2c, srcC, rowC, aggrC, C);
        gather_kernel<<<(L + 7) / 8, 256>>>(Mc2l, srcL, rowL, aggrL, L);

        // updates
        mlp_tc<2, false><<<g2C, 256, sm2>>>(ce, aggrC, nullptr,
            W[3][0], W[3][1], W[3][2], W[3][3], nce,
            nullptr, nullptr, nullptr, nullptr, nullptr, C);
        mlp_tc<3, false><<<g3L, 256, sm3>>>(le, aggrL, Ml2l,
            W[4][0], W[4][1], W[4][2], W[4][3], nle,
            nullptr, nullptr, nullptr, nullptr, nullptr, L);
    }
    (void)out_size;
}

// round 16
// speedup vs baseline: 1.0960x; 1.0738x over previous
#include <cuda_runtime.h>
#include <cuda_fp16.h>
#include <cstdint>

#define DIM 64
#define LMAX 200000
#define CMAX 80000
#define EMAX 1100000
#define SCAN_NB 256

// -------- scratch (static __device__ arrays; no allocation allowed) --------
__device__ float g_Ml2c[(size_t)LMAX * DIM];   // 51.2 MB
__device__ float g_Mc2l[(size_t)CMAX * DIM];   // 20.5 MB
__device__ float g_Ml2l[(size_t)LMAX * DIM];   // 51.2 MB
__device__ float g_aggrC[(size_t)CMAX * DIM];  // 20.5 MB
__device__ float g_aggrL[(size_t)LMAX * DIM];  // 51.2 MB
// CSR scratch
__device__ int g_cntC[CMAX],  g_rowC[CMAX + 1], g_curC[CMAX], g_srcC[EMAX];
__device__ int g_cntL[LMAX],  g_rowL[LMAX + 1], g_curL[LMAX], g_srcL[EMAX];
__device__ int g_bsumC[SCAN_NB], g_bsumL[SCAN_NB];

// ---------------------------------------------------------------------------
__device__ __forceinline__ void mma_16816(float* d, const uint32_t* a,
                                          const uint32_t* b)
{
    asm volatile(
        "mma.sync.aligned.m16n8k16.row.col.f32.f16.f16.f32 "
        "{%0,%1,%2,%3}, {%4,%5,%6,%7}, {%8,%9}, {%0,%1,%2,%3};\n"
        : "+f"(d[0]), "+f"(d[1]), "+f"(d[2]), "+f"(d[3])
        : "r"(a[0]), "r"(a[1]), "r"(a[2]), "r"(a[3]), "r"(b[0]), "r"(b[1]));
}

// ---------------------------------------------------------------------------
__device__ __forceinline__ void init_bias_frag(float a[2][4][4], const float* b,
                                               int wn, int tig)
{
    #pragma unroll
    for (int nt = 0; nt < 4; ++nt) {
        float bv0 = b[wn + nt * 8 + 2 * tig];
        float bv1 = b[wn + nt * 8 + 2 * tig + 1];
        #pragma unroll
        for (int mt = 0; mt < 2; ++mt) {
            a[mt][nt][0] = bv0; a[mt][nt][1] = bv1;
            a[mt][nt][2] = bv0; a[mt][nt][3] = bv1;
        }
    }
}

// acc += A[128x64 tile rows] @ (Wh+Wl)  over one 64-wide K segment
__device__ __forceinline__ void mma_accum_64(
    float acc[2][4][4],
    const __half* __restrict__ A,      // [128][72] halves
    const __half* __restrict__ Wh, const __half* __restrict__ Wl,
    int wstride, int koff,
    int wm, int wn, int gid, int tig)
{
    #pragma unroll
    for (int kb = 0; kb < 4; ++kb) {
        const int k0 = kb * 16;
        uint32_t ah[2][4];
        #pragma unroll
        for (int mt = 0; mt < 2; ++mt) {
            int r0 = (wm + mt * 16 + gid) * 72;
            int r8 = r0 + 8 * 72;
            ah[mt][0] = *(const uint32_t*)(A + r0 + k0 + 2 * tig);
            ah[mt][1] = *(const uint32_t*)(A + r8 + k0 + 2 * tig);
            ah[mt][2] = *(const uint32_t*)(A + r0 + k0 + 2 * tig + 8);
            ah[mt][3] = *(const uint32_t*)(A + r8 + k0 + 2 * tig + 8);
        }
        uint32_t bh[4][2], bl[4][2];
        #pragma unroll
        for (int nt = 0; nt < 4; ++nt) {
            int n = (wn + nt * 8 + gid) * wstride + koff + k0;
            bh[nt][0] = *(const uint32_t*)(Wh + n + 2 * tig);
            bh[nt][1] = *(const uint32_t*)(Wh + n + 2 * tig + 8);
            bl[nt][0] = *(const uint32_t*)(Wl + n + 2 * tig);
            bl[nt][1] = *(const uint32_t*)(Wl + n + 2 * tig + 8);
        }
        #pragma unroll
        for (int nt = 0; nt < 4; ++nt) {
            mma_16816(acc[0][nt], ah[0], bh[nt]);
            mma_16816(acc[1][nt], ah[1], bh[nt]);
        }
        #pragma unroll
        for (int nt = 0; nt < 4; ++nt) {
            mma_16816(acc[0][nt], ah[0], bl[nt]);
            mma_16816(acc[1][nt], ah[1], bl[nt]);
        }
    }
}

__device__ __forceinline__ void relu_to_smem(const float a[2][4][4], __half* Hs,
                                             int wm, int wn, int gid, int tig)
{
    #pragma unroll
    for (int mt = 0; mt < 2; ++mt)
        #pragma unroll
        for (int nt = 0; nt < 4; ++nt) {
            int r0 = wm + mt * 16 + gid;
            int c0 = wn + nt * 8 + 2 * tig;
            *(__half2*)(Hs + r0 * 72 + c0) =
                __floats2half2_rn(fmaxf(a[mt][nt][0], 0.f), fmaxf(a[mt][nt][1], 0.f));
            *(__half2*)(Hs + (r0 + 8) * 72 + c0) =
                __floats2half2_rn(fmaxf(a[mt][nt][2], 0.f), fmaxf(a[mt][nt][3], 0.f));
        }
}

__device__ __forceinline__ void epilogue_store(const float o[2][4][4], float* out,
                                               int base, int nrows, bool flip,
                                               int wm, int wn, int gid, int tig)
{
    #pragma unroll
    for (int mt = 0; mt < 2; ++mt)
        #pragma unroll
        for (int nt = 0; nt < 4; ++nt) {
            int r = base + wm + mt * 16 + gid;
            int c = wn + nt * 8 + 2 * tig;
            if (r < nrows) {
                int ro = flip ? (r ^ 1) : r;
                *(float2*)(out + (size_t)ro * 64 + c) =
                    make_float2(o[mt][nt][0], o[mt][nt][1]);
            }
            if (r + 8 < nrows) {
                int ro = flip ? ((r + 8) ^ 1) : (r + 8);
                *(float2*)(out + (size_t)ro * 64 + c) =
                    make_float2(o[mt][nt][2], o[mt][nt][3]);
            }
        }
}

// ---------------------------------------------------------------------------
// 2-term fp16-split MLP, 128-row tiles, 256 threads, register-prefetch.
// EXACT R11 kernel (validated 624.7us / rel_err 1.233e-4): (256,2), separate Hs.
// FUSE: second MLP (weights b) on the same staged X, output pair-flipped.
// ---------------------------------------------------------------------------
template <int PARTS, bool FUSE>
__global__ __launch_bounds__(256, 2) void mlp_tc(
    const float* __restrict__ x0, const float* __restrict__ x1,
    const float* __restrict__ x2,
    const float* __restrict__ W1a, const float* __restrict__ b1a,
    const float* __restrict__ W2a, const float* __restrict__ b2a,
    float* __restrict__ outA,
    const float* __restrict__ W1b, const float* __restrict__ b1b,
    const float* __restrict__ W2b, const float* __restrict__ b2b,
    float* __restrict__ outB,
    int nrows)
{
    constexpr int K  = PARTS * 64;
    constexpr int WS = K + 8;

    extern __shared__ __half smh[];
    __half* W1ah = smh;                       // [64][WS]
    __half* W1al = W1ah + 64 * WS;
    __half* W2ah = W1al + 64 * WS;            // [64][72]
    __half* W2al = W2ah + 64 * 72;
    __half* W1bh = W2al + 64 * 72;            // FUSE only (K=64, stride 72)
    __half* W1bl = W1bh + (FUSE ? 64 * 72 : 0);
    __half* W2bh = W1bl + (FUSE ? 64 * 72 : 0);
    __half* W2bl = W2bh + (FUSE ? 64 * 72 : 0);
    __half* Xs   = W2bl + (FUSE ? 64 * 72 : 0);   // [128][72]
    __half* Hs   = Xs + 128 * 72;                 // [128][72]
    float*  bias = (float*)(Hs + 128 * 72);       // b1a,b2a[,b1b,b2b] x64

    const int tid = threadIdx.x;
    for (int i = tid; i < K * 64; i += 256) {
        int k = i >> 6, n = i & 63;
        float w = W1a[i];
        __half hi = __float2half_rn(w);
        W1ah[n * WS + k] = hi;
        W1al[n * WS + k] = __float2half_rn(w - __half2float(hi));
    }
    for (int i = tid; i < 64 * 64; i += 256) {
        int k = i >> 6, n = i & 63;
        float w = W2a[i];
        __half hi = __float2half_rn(w);
        W2ah[n * 72 + k] = hi;
        W2al[n * 72 + k] = __float2half_rn(w - __half2float(hi));
    }
    if (FUSE) {
        for (int i = tid; i < 64 * 64; i += 256) {
            int k = i >> 6, n = i & 63;
            float w = W1b[i];
            __half hi = __float2half_rn(w);
            W1bh[n * 72 + k] = hi;
            W1bl[n * 72 + k] = __float2half_rn(w - __half2float(hi));
            float w2 = W2b[i];
            __half h2 = __float2half_rn(w2);
            W2bh[n * 72 + k] = h2;
            W2bl[n * 72 + k] = __float2half_rn(w2 - __half2float(h2));
        }
    }
    if (tid < 64) {
        bias[tid] = b1a[tid]; bias[64 + tid] = b2a[tid];
        if (FUSE) { bias[128 + tid] = b1b[tid]; bias[192 + tid] = b2b[tid]; }
    }
    __syncthreads();   // weights+bias visible to all warps (R3/R4 lesson)

    const int lane = tid & 31;
    const int warp = tid >> 5;
    const int gid = lane >> 2, tig = lane & 3;
    const int wm = (warp & 3) * 32;   // 4 m-quadrants over 128 rows
    const int wn = (warp >> 2) * 32;  // 2 n-quadrants over 64 cols

    const int ntiles = (nrows + 127) >> 7;
    int tile = blockIdx.x;
    float2 pf[16];
    if (tile < ntiles) {   // prologue prefetch: (tile, part 0)
        #pragma unroll
        for (int i = 0; i < 16; ++i) {
            int idx = tid + i * 256;
            int r = idx >> 5, kp = idx & 31;
            int row = (tile << 7) + r;
            pf[i] = (row < nrows) ? *(const float2*)(x0 + (size_t)row * 64 + 2 * kp)
                                  : make_float2(0.f, 0.f);
        }
    }

    for (; tile < ntiles; tile += gridDim.x) {
        const int base = tile << 7;
        float acc[2][4][4];
        init_bias_frag(acc, bias, wn, tig);

        #pragma unroll
        for (int p = 0; p < PARTS; ++p) {
            __syncthreads();   // Xs (and Hs via barrier transitivity) reusable
            #pragma unroll
            for (int i = 0; i < 16; ++i) {
                int idx = tid + i * 256;
                int r = idx >> 5, kp = idx & 31;
                *(__half2*)(Xs + r * 72 + 2 * kp) = __floats2half2_rn(pf[i].x, pf[i].y);
            }
            __syncthreads();
            // prefetch next stage while MMAs run (hides gmem latency)
            int np = p + 1;
            int ntile = tile;
            if (np == PARTS) { np = 0; ntile = tile + (int)gridDim.x; }
            if (ntile < ntiles) {
                const float* nx = (np == 0) ? x0 : ((np == 1) ? x1 : x2);
                int nb = ntile << 7;
                #pragma unroll
                for (int i = 0; i < 16; ++i) {
                    int idx = tid + i * 256;
                    int r = idx >> 5, kp = idx & 31;
                    int row = nb + r;
                    pf[i] = (row < nrows)
                          ? *(const float2*)(nx + (size_t)row * 64 + 2 * kp)
                          : make_float2(0.f, 0.f);
                }
            }
            mma_accum_64(acc, Xs, W1ah, W1al, WS, p * 64, wm, wn, gid, tig);
        }

        relu_to_smem(acc, Hs, wm, wn, gid, tig);
        __syncthreads();
        float o[2][4][4];
        init_bias_frag(o, bias + 64, wn, tig);
        mma_accum_64(o, Hs, W2ah, W2al, 72, 0, wm, wn, gid, tig);
        epilogue_store(o, outA, base, nrows, false, wm, wn, gid, tig);

        if (FUSE) {
            __syncthreads();   // all warps done reading Hs before it is rewritten
            float acc2[2][4][4];
            init_bias_frag(acc2, bias + 128, wn, tig);
            mma_accum_64(acc2, Xs, W1bh, W1bl, 72, 0, wm, wn, gid, tig);
            relu_to_smem(acc2, Hs, wm, wn, gid, tig);
            __syncthreads();
            float o2[2][4][4];
            init_bias_frag(o2, bias + 192, wn, tig);
            mma_accum_64(o2, Hs, W2bh, W2bl, 72, 0, wm, wn, gid, tig);
            epilogue_store(o2, outB, base, nrows, true, wm, wn, gid, tig);
        }
    }
}

// ---------------------------------------------------------------------------
// CSR build: fused count (both CSRs per edge pass) -> scans -> fused place
// ---------------------------------------------------------------------------
__global__ void count2_kernel(const int* __restrict__ ce, const int* __restrict__ le,
                              int E, int* __restrict__ cntC, int* __restrict__ cntL)
{
    int e = blockIdx.x * 256 + threadIdx.x;
    if (e < E) {
        atomicAdd(&cntC[ce[e]], 1);
        atomicAdd(&cntL[le[e]], 1);
    }
}

__global__ void scan_reduce(const int* __restrict__ cnt, int n, int* __restrict__ bsum)
{
    int b = blockIdx.x;
    int CH = (n + SCAN_NB - 1) / SCAN_NB;
    int s = b * CH, e = min(n, s + CH);
    __shared__ int sh[256];
    int t = threadIdx.x, sum = 0;
    for (int i = s + t; i < e; i += 256) sum += cnt[i];
    sh[t] = sum; __syncthreads();
    for (int o = 128; o > 0; o >>= 1) {
        if (t < o) sh[t] += sh[t + o];
        __syncthreads();
    }
    if (t == 0) bsum[b] = sh[0];
}

__global__ void scan_bsum(int* __restrict__ bsum)
{
    __shared__ int sh[256];
    int t = threadIdx.x;
    sh[t] = bsum[t]; __syncthreads();
    for (int o = 1; o < 256; o <<= 1) {
        int v = (t >= o) ? sh[t - o] : 0;
        __syncthreads();
        sh[t] += v;
        __syncthreads();
    }
    bsum[t] = (t == 0) ? 0 : sh[t - 1];
}

__global__ void scan_write(const int* __restrict__ cnt, int n,
                           const int* __restrict__ bsum, int* __restrict__ rowptr, int total)
{
    int b = blockIdx.x;
    int CH = (n + SCAN_NB - 1) / SCAN_NB;
    int s = b * CH, e = min(n, s + CH);
    int t = threadIdx.x;
    int per = (CH + 255) / 256;
    int ts = min(e, s + t * per), te = min(e, s + t * per + per);
    int sum = 0;
    for (int i = ts; i < te; ++i) sum += cnt[i];
    __shared__ int sh[256];
    sh[t] = sum; __syncthreads();
    for (int o = 1; o < 256; o <<= 1) {
        int v = (t >= o) ? sh[t - o] : 0;
        __syncthreads();
        sh[t] += v;
        __syncthreads();
    }
    int off = bsum[b] + ((t == 0) ? 0 : sh[t - 1]);
    for (int i = ts; i < te; ++i) { rowptr[i] = off; off += cnt[i]; }
    if (b == 0 && t == 0) rowptr[n] = total;
}

__global__ void place2_kernel(const int* __restrict__ ce, const int* __restrict__ le,
                              int E, int* __restrict__ curC, int* __restrict__ srcC,
                              int* __restrict__ curL, int* __restrict__ srcL)
{
    int e = blockIdx.x * 256 + threadIdx.x;
    if (e < E) {
        int c = ce[e], l = le[e];
        srcC[atomicAdd(&curC[c], 1)] = l;
        srcL[atomicAdd(&curL[l], 1)] = c;
    }
}

// ---------------------------------------------------------------------------
// Gather aggregation (R11-validated): 16 lanes/dest, float4 per lane.
// Simple dependent loop — every "smarter" variant (fp16, warp-per-dest with
// prefetch) measured slower. Do not redesign without per-kernel profile data.
// ---------------------------------------------------------------------------
__global__ __launch_bounds__(256) void gather_kernel(
    const float* __restrict__ src, const int* __restrict__ srcidx,
    const int* __restrict__ rowptr, float* __restrict__ dst, int n)
{
    int d = blockIdx.x * 16 + (threadIdx.x >> 4);
    int q = threadIdx.x & 15;
    if (d >= n) return;
    int s = rowptr[d], e = rowptr[d + 1];
    float ax = 0.f, ay = 0.f, az = 0.f, aw = 0.f;
    for (int i = s; i < e; ++i) {
        int r = __ldg(srcidx + i);
        float4 v = *(const float4*)(src + (size_t)r * 64 + q * 4);
        ax += v.x; ay += v.y; az += v.z; aw += v.w;
    }
    *(float4*)(dst + (size_t)d * 64 + q * 4) = make_float4(ax, ay, az, aw);
}

// ---------------------------------------------------------------------------
static inline size_t mlp_smem_bytes(int parts, bool fuse)
{
    size_t WS = parts * 64 + 8;
    size_t halves = 2 * 64 * WS + 2 * 64 * 72 + (fuse ? 4 * 64 * 72 : 0)
                  + (size_t)2 * 128 * 72;
    return halves * 2 + 256 * sizeof(float);
}

extern "C" void kernel_launch(void* const* d_in, const int* in_sizes, int n_in,
                              void* d_out, int out_size)
{
    const int off = n_in - 24;
    const int* l_edge = (const int*)d_in[off + 0];
    const int* c_edge = (const int*)d_in[off + 1];
    const float* l_emb_in = (const float*)d_in[off + 2];
    const float* c_emb_in = (const float*)d_in[off + 3];
    const int E = in_sizes[off + 0];
    const int L = in_sizes[off + 2] / DIM;
    const int C = in_sizes[off + 3] / DIM;

    const float* W[5][4];
    for (int m = 0; m < 5; ++m)
        for (int j = 0; j < 4; ++j)
            W[m][j] = (const float*)d_in[off + 4 + m * 4 + j];
    // m: 0=l2c, 1=c2l, 2=l2l, 3=cu, 4=lu

    float* Ml2c, * Mc2l, * Ml2l, * aggrC, * aggrL;
    int *cntC, *rowC, *curC, *srcC, *bsC;
    int *cntL, *rowL, *curL, *srcL, *bsL;
    cudaGetSymbolAddress((void**)&Ml2c, g_Ml2c);
    cudaGetSymbolAddress((void**)&Mc2l, g_Mc2l);
    cudaGetSymbolAddress((void**)&Ml2l, g_Ml2l);
    cudaGetSymbolAddress((void**)&aggrC, g_aggrC);
    cudaGetSymbolAddress((void**)&aggrL, g_aggrL);
    cudaGetSymbolAddress((void**)&cntC, g_cntC);
    cudaGetSymbolAddress((void**)&rowC, g_rowC);
    cudaGetSymbolAddress((void**)&curC, g_curC);
    cudaGetSymbolAddress((void**)&srcC, g_srcC);
    cudaGetSymbolAddress((void**)&bsC,  g_bsumC);
    cudaGetSymbolAddress((void**)&cntL, g_cntL);
    cudaGetSymbolAddress((void**)&rowL, g_rowL);
    cudaGetSymbolAddress((void**)&curL, g_curL);
    cudaGetSymbolAddress((void**)&srcL, g_srcL);
    cudaGetSymbolAddress((void**)&bsL,  g_bsumL);

    const size_t smF = mlp_smem_bytes(1, true);
    const size_t sm1 = mlp_smem_bytes(1, false);
    const size_t sm2 = mlp_smem_bytes(2, false);
    const size_t sm3 = mlp_smem_bytes(3, false);
    cudaFuncSetAttribute(mlp_tc<1, true>,  cudaFuncAttributeMaxDynamicSharedMemorySize, (int)smF);
    cudaFuncSetAttribute(mlp_tc<1, false>, cudaFuncAttributeMaxDynamicSharedMemorySize, (int)sm1);
    cudaFuncSetAttribute(mlp_tc<2, false>, cudaFuncAttributeMaxDynamicSharedMemorySize, (int)sm2);
    cudaFuncSetAttribute(mlp_tc<3, false>, cudaFuncAttributeMaxDynamicSharedMemorySize, (int)sm3);

    float* outBase = (float*)d_out;
    float* outL = outBase;                          // (3, L, 64)
    float* outC = outBase + (size_t)3 * L * DIM;    // (3, C, 64)

    cudaMemcpyAsync(outL, l_emb_in, (size_t)L * DIM * sizeof(float), cudaMemcpyDeviceToDevice);
    cudaMemcpyAsync(outC, c_emb_in, (size_t)C * DIM * sizeof(float), cudaMemcpyDeviceToDevice);

    // ---- CSR build (fused per-edge passes; single variable vs R11) ----
    const int eb = (E + 255) / 256;
    cudaMemsetAsync(cntC, 0, C * sizeof(int));
    cudaMemsetAsync(cntL, 0, L * sizeof(int));
    count2_kernel<<<eb, 256>>>(c_edge, l_edge, E, cntC, cntL);
    scan_reduce<<<SCAN_NB, 256>>>(cntC, C, bsC);
    scan_reduce<<<SCAN_NB, 256>>>(cntL, L, bsL);
    scan_bsum<<<1, 256>>>(bsC);
    scan_bsum<<<1, 256>>>(bsL);
    scan_write<<<SCAN_NB, 256>>>(cntC, C, bsC, rowC, E);
    scan_write<<<SCAN_NB, 256>>>(cntL, L, bsL, rowL, E);
    cudaMemcpyAsync(curC, rowC, C * sizeof(int), cudaMemcpyDeviceToDevice);
    cudaMemcpyAsync(curL, rowL, L * sizeof(int), cudaMemcpyDeviceToDevice);
    place2_kernel<<<eb, 256>>>(c_edge, l_edge, E, curC, srcC, curL, srcL);

    const int ltiles = (L + 127) >> 7;
    const int ctiles = (C + 127) >> 7;
    auto gridFor = [](int tiles, int maxResident) {
        return tiles < maxResident ? tiles : maxResident;
    };
    const int gF  = gridFor(ltiles, 148 * 2);
    const int g1C = gridFor(ctiles, 148 * 2);
    const int g2C = gridFor(ctiles, 148 * 2);
    const int g3L = gridFor(ltiles, 148 * 2);

    for (int t = 0; t < 2; ++t) {
        const float* le = outL + (size_t)t * L * DIM;
        const float* ce = outC + (size_t)t * C * DIM;
        float* nle = outL + (size_t)(t + 1) * L * DIM;
        float* nce = outC + (size_t)(t + 1) * C * DIM;

        // fused messages from le: l2c (plain) + l2l (flipped output)
        mlp_tc<1, true><<<gF, 256, smF>>>(le, nullptr, nullptr,
            W[0][0], W[0][1], W[0][2], W[0][3], Ml2c,
            W[2][0], W[2][1], W[2][2], W[2][3], Ml2l, L);
        // c2l from ce
        mlp_tc<1, false><<<g1C, 256, sm1>>>(ce, nullptr, nullptr,
            W[1][0], W[1][1], W[1][2], W[1][3], Mc2l,
            nullptr, nullptr, nullptr, nullptr, nullptr, C);

        // aggregation via half-warp gather (R11-validated)
        gather_kernel<<<(C + 15) / 16, 256>>>(Ml2c, srcC, rowC, aggrC, C);
        gather_kernel<<<(L + 15) / 16, 256>>>(Mc2l, srcL, rowL, aggrL, L);

        // updates
        mlp_tc<2, false><<<g2C, 256, sm2>>>(ce, aggrC, nullptr,
            W[3][0], W[3][1], W[3][2], W[3][3], nce,
            nullptr, nullptr, nullptr, nullptr, nullptr, C);
        mlp_tc<3, false><<<g3L, 256, sm3>>>(le, aggrL, Ml2l,
            W[4][0], W[4][1], W[4][2], W[4][3], nle,
            nullptr, nullptr, nullptr, nullptr, nullptr, L);
    }
    (void)out_size;
}

// round 17
// speedup vs baseline: 1.1542x; 1.0532x over previous
#include <cuda_runtime.h>
#include <cuda_fp16.h>
#include <cstdint>

#define DIM 64
#define LMAX 200000
#define CMAX 80000
#define EMAX 1100000
#define SCAN_NB 256

// -------- scratch (static __device__ arrays; no allocation allowed) --------
__device__ float g_Ml2c[(size_t)LMAX * DIM];
__device__ float g_Mc2l[(size_t)CMAX * DIM];
__device__ float g_Ml2l[(size_t)LMAX * DIM];
__device__ float g_aggrC[(size_t)CMAX * DIM];
__device__ float g_aggrL[(size_t)LMAX * DIM];
// CSR scratch
__device__ int g_cntC[CMAX],  g_rowC[CMAX + 1], g_curC[CMAX], g_srcC[EMAX];
__device__ int g_cntL[LMAX],  g_rowL[LMAX + 1], g_curL[LMAX], g_srcL[EMAX];
__device__ int g_bsumC[SCAN_NB], g_bsumL[SCAN_NB];

// ---------------------------------------------------------------------------
__device__ __forceinline__ void mma_16816(float* d, const uint32_t* a,
                                          const uint32_t* b)
{
    asm volatile(
        "mma.sync.aligned.m16n8k16.row.col.f32.f16.f16.f32 "
        "{%0,%1,%2,%3}, {%4,%5,%6,%7}, {%8,%9}, {%0,%1,%2,%3};\n"
        : "+f"(d[0]), "+f"(d[1]), "+f"(d[2]), "+f"(d[3])
        : "r"(a[0]), "r"(a[1]), "r"(a[2]), "r"(a[3]), "r"(b[0]), "r"(b[1]));
}

__device__ __forceinline__ void init_bias_frag(float a[2][4][4], const float* b,
                                               int wn, int tig)
{
    #pragma unroll
    for (int nt = 0; nt < 4; ++nt) {
        float bv0 = b[wn + nt * 8 + 2 * tig];
        float bv1 = b[wn + nt * 8 + 2 * tig + 1];
        #pragma unroll
        for (int mt = 0; mt < 2; ++mt) {
            a[mt][nt][0] = bv0; a[mt][nt][1] = bv1;
            a[mt][nt][2] = bv0; a[mt][nt][3] = bv1;
        }
    }
}

__device__ __forceinline__ void mma_accum_64(
    float acc[2][4][4],
    const __half* __restrict__ A,
    const __half* __restrict__ Wh, const __half* __restrict__ Wl,
    int wstride, int koff,
    int wm, int wn, int gid, int tig)
{
    #pragma unroll
    for (int kb = 0; kb < 4; ++kb) {
        const int k0 = kb * 16;
        uint32_t ah[2][4];
        #pragma unroll
        for (int mt = 0; mt < 2; ++mt) {
            int r0 = (wm + mt * 16 + gid) * 72;
            int r8 = r0 + 8 * 72;
            ah[mt][0] = *(const uint32_t*)(A + r0 + k0 + 2 * tig);
            ah[mt][1] = *(const uint32_t*)(A + r8 + k0 + 2 * tig);
            ah[mt][2] = *(const uint32_t*)(A + r0 + k0 + 2 * tig + 8);
            ah[mt][3] = *(const uint32_t*)(A + r8 + k0 + 2 * tig + 8);
        }
        uint32_t bh[4][2], bl[4][2];
        #pragma unroll
        for (int nt = 0; nt < 4; ++nt) {
            int n = (wn + nt * 8 + gid) * wstride + koff + k0;
            bh[nt][0] = *(const uint32_t*)(Wh + n + 2 * tig);
            bh[nt][1] = *(const uint32_t*)(Wh + n + 2 * tig + 8);
            bl[nt][0] = *(const uint32_t*)(Wl + n + 2 * tig);
            bl[nt][1] = *(const uint32_t*)(Wl + n + 2 * tig + 8);
        }
        #pragma unroll
        for (int nt = 0; nt < 4; ++nt) {
            mma_16816(acc[0][nt], ah[0], bh[nt]);
            mma_16816(acc[1][nt], ah[1], bh[nt]);
        }
        #pragma unroll
        for (int nt = 0; nt < 4; ++nt) {
            mma_16816(acc[0][nt], ah[0], bl[nt]);
            mma_16816(acc[1][nt], ah[1], bl[nt]);
        }
    }
}

__device__ __forceinline__ void relu_to_smem(const float a[2][4][4], __half* Hs,
                                             int wm, int wn, int gid, int tig)
{
    #pragma unroll
    for (int mt = 0; mt < 2; ++mt)
        #pragma unroll
        for (int nt = 0; nt < 4; ++nt) {
            int r0 = wm + mt * 16 + gid;
            int c0 = wn + nt * 8 + 2 * tig;
            *(__half2*)(Hs + r0 * 72 + c0) =
                __floats2half2_rn(fmaxf(a[mt][nt][0], 0.f), fmaxf(a[mt][nt][1], 0.f));
            *(__half2*)(Hs + (r0 + 8) * 72 + c0) =
                __floats2half2_rn(fmaxf(a[mt][nt][2], 0.f), fmaxf(a[mt][nt][3], 0.f));
        }
}

__device__ __forceinline__ void epilogue_store(const float o[2][4][4], float* out,
                                               int base, int nrows, bool flip,
                                               int wm, int wn, int gid, int tig)
{
    #pragma unroll
    for (int mt = 0; mt < 2; ++mt)
        #pragma unroll
        for (int nt = 0; nt < 4; ++nt) {
            int r = base + wm + mt * 16 + gid;
            int c = wn + nt * 8 + 2 * tig;
            if (r < nrows) {
                int ro = flip ? (r ^ 1) : r;
                *(float2*)(out + (size_t)ro * 64 + c) =
                    make_float2(o[mt][nt][0], o[mt][nt][1]);
            }
            if (r + 8 < nrows) {
                int ro = flip ? ((r + 8) ^ 1) : (r + 8);
                *(float2*)(out + (size_t)ro * 64 + c) =
                    make_float2(o[mt][nt][2], o[mt][nt][3]);
            }
        }
}

// ---------------------------------------------------------------------------
// R11-validated MLP body, refactored to take a virtual block id/grid so that
// merged kernels can interleave independent MLPs at block granularity.
// ---------------------------------------------------------------------------
template <int PARTS, bool FUSE>
__device__ void mlp_body(
    int vb, int vgrid,
    const float* __restrict__ x0, const float* __restrict__ x1,
    const float* __restrict__ x2,
    const float* __restrict__ W1a, const float* __restrict__ b1a,
    const float* __restrict__ W2a, const float* __restrict__ b2a,
    float* __restrict__ outA,
    const float* __restrict__ W1b, const float* __restrict__ b1b,
    const float* __restrict__ W2b, const float* __restrict__ b2b,
    float* __restrict__ outB,
    int nrows, __half* smh)
{
    constexpr int K  = PARTS * 64;
    constexpr int WS = K + 8;

    __half* W1ah = smh;
    __half* W1al = W1ah + 64 * WS;
    __half* W2ah = W1al + 64 * WS;
    __half* W2al = W2ah + 64 * 72;
    __half* W1bh = W2al + 64 * 72;
    __half* W1bl = W1bh + (FUSE ? 64 * 72 : 0);
    __half* W2bh = W1bl + (FUSE ? 64 * 72 : 0);
    __half* W2bl = W2bh + (FUSE ? 64 * 72 : 0);
    __half* Xs   = W2bl + (FUSE ? 64 * 72 : 0);
    __half* Hs   = Xs + 128 * 72;
    float*  bias = (float*)(Hs + 128 * 72);

    const int tid = threadIdx.x;
    for (int i = tid; i < K * 64; i += 256) {
        int k = i >> 6, n = i & 63;
        float w = W1a[i];
        __half hi = __float2half_rn(w);
        W1ah[n * WS + k] = hi;
        W1al[n * WS + k] = __float2half_rn(w - __half2float(hi));
    }
    for (int i = tid; i < 64 * 64; i += 256) {
        int k = i >> 6, n = i & 63;
        float w = W2a[i];
        __half hi = __float2half_rn(w);
        W2ah[n * 72 + k] = hi;
        W2al[n * 72 + k] = __float2half_rn(w - __half2float(hi));
    }
    if (FUSE) {
        for (int i = tid; i < 64 * 64; i += 256) {
            int k = i >> 6, n = i & 63;
            float w = W1b[i];
            __half hi = __float2half_rn(w);
            W1bh[n * 72 + k] = hi;
            W1bl[n * 72 + k] = __float2half_rn(w - __half2float(hi));
            float w2 = W2b[i];
            __half h2 = __float2half_rn(w2);
            W2bh[n * 72 + k] = h2;
            W2bl[n * 72 + k] = __float2half_rn(w2 - __half2float(h2));
        }
    }
    if (tid < 64) {
        bias[tid] = b1a[tid]; bias[64 + tid] = b2a[tid];
        if (FUSE) { bias[128 + tid] = b1b[tid]; bias[192 + tid] = b2b[tid]; }
    }
    __syncthreads();   // weights+bias visible to all warps (R3/R4 lesson)

    const int lane = tid & 31;
    const int warp = tid >> 5;
    const int gid = lane >> 2, tig = lane & 3;
    const int wm = (warp & 3) * 32;
    const int wn = (warp >> 2) * 32;

    const int ntiles = (nrows + 127) >> 7;
    int tile = vb;
    float2 pf[16];
    if (tile < ntiles) {
        #pragma unroll
        for (int i = 0; i < 16; ++i) {
            int idx = tid + i * 256;
            int r = idx >> 5, kp = idx & 31;
            int row = (tile << 7) + r;
            pf[i] = (row < nrows) ? *(const float2*)(x0 + (size_t)row * 64 + 2 * kp)
                                  : make_float2(0.f, 0.f);
        }
    }

    for (; tile < ntiles; tile += vgrid) {
        const int base = tile << 7;
        float acc[2][4][4];
        init_bias_frag(acc, bias, wn, tig);

        #pragma unroll
        for (int p = 0; p < PARTS; ++p) {
            __syncthreads();
            #pragma unroll
            for (int i = 0; i < 16; ++i) {
                int idx = tid + i * 256;
                int r = idx >> 5, kp = idx & 31;
                *(__half2*)(Xs + r * 72 + 2 * kp) = __floats2half2_rn(pf[i].x, pf[i].y);
            }
            __syncthreads();
            int np = p + 1;
            int ntile = tile;
            if (np == PARTS) { np = 0; ntile = tile + vgrid; }
            if (ntile < ntiles) {
                const float* nx = (np == 0) ? x0 : ((np == 1) ? x1 : x2);
                int nb = ntile << 7;
                #pragma unroll
                for (int i = 0; i < 16; ++i) {
                    int idx = tid + i * 256;
                    int r = idx >> 5, kp = idx & 31;
                    int row = nb + r;
                    pf[i] = (row < nrows)
                          ? *(const float2*)(nx + (size_t)row * 64 + 2 * kp)
                          : make_float2(0.f, 0.f);
                }
            }
            mma_accum_64(acc, Xs, W1ah, W1al, WS, p * 64, wm, wn, gid, tig);
        }

        relu_to_smem(acc, Hs, wm, wn, gid, tig);
        __syncthreads();
        float o[2][4][4];
        init_bias_frag(o, bias + 64, wn, tig);
        mma_accum_64(o, Hs, W2ah, W2al, 72, 0, wm, wn, gid, tig);
        epilogue_store(o, outA, base, nrows, false, wm, wn, gid, tig);

        if (FUSE) {
            __syncthreads();
            float acc2[2][4][4];
            init_bias_frag(acc2, bias + 128, wn, tig);
            mma_accum_64(acc2, Xs, W1bh, W1bl, 72, 0, wm, wn, gid, tig);
            relu_to_smem(acc2, Hs, wm, wn, gid, tig);
            __syncthreads();
            float o2[2][4][4];
            init_bias_frag(o2, bias + 192, wn, tig);
            mma_accum_64(o2, Hs, W2bh, W2bl, 72, 0, wm, wn, gid, tig);
            epilogue_store(o2, outB, base, nrows, true, wm, wn, gid, tig);
        }
    }
}

// ---------------------------------------------------------------------------
// Merged message kernel: blocks r<5 of 6 -> fused l2c/l2l over L;
// r==5 -> c2l over C. Grid must be divisible by 6.
// ---------------------------------------------------------------------------
__global__ __launch_bounds__(256, 2) void mlp_msg(
    const float* __restrict__ le, const float* __restrict__ ce,
    const float* W0a, const float* W0b, const float* W0c, const float* W0d,
    const float* W2a, const float* W2b, const float* W2c, const float* W2d,
    const float* W1a, const float* W1b, const float* W1c, const float* W1d,
    float* Ml2c, float* Ml2l, float* Mc2l, int L, int C)
{
    extern __shared__ __half smh[];
    int b = blockIdx.x;
    int g = b / 6, r = b - g * 6;
    int G = gridDim.x / 6;
    if (r < 5) {
        mlp_body<1, true>(g * 5 + r, G * 5, le, nullptr, nullptr,
                          W0a, W0b, W0c, W0d, Ml2c,
                          W2a, W2b, W2c, W2d, Ml2l, L, smh);
    } else {
        mlp_body<1, false>(g, G, ce, nullptr, nullptr,
                           W1a, W1b, W1c, W1d, Mc2l,
                           nullptr, nullptr, nullptr, nullptr, nullptr, C, smh);
    }
}

// ---------------------------------------------------------------------------
// Merged update kernel: blocks r<3 of 4 -> lu (parts=3) over L;
// r==3 -> cu (parts=2) over C. Grid must be divisible by 4.
// ---------------------------------------------------------------------------
__global__ __launch_bounds__(256, 2) void mlp_upd(
    const float* __restrict__ le, const float* __restrict__ ce,
    const float* __restrict__ aggrL, const float* __restrict__ aggrC,
    const float* __restrict__ Ml2l,
    const float* W4a, const float* W4b, const float* W4c, const float* W4d,
    const float* W3a, const float* W3b, const float* W3c, const float* W3d,
    float* nle, float* nce, int L, int C)
{
    extern __shared__ __half smh[];
    int b = blockIdx.x;
    int g = b >> 2, r = b & 3;
    int G = gridDim.x >> 2;
    if (r < 3) {
        mlp_body<3, false>(g * 3 + r, G * 3, le, aggrL, Ml2l,
                           W4a, W4b, W4c, W4d, nle,
                           nullptr, nullptr, nullptr, nullptr, nullptr, L, smh);
    } else {
        mlp_body<2, false>(g, G, ce, aggrC, nullptr,
                           W3a, W3b, W3c, W3d, nce,
                           nullptr, nullptr, nullptr, nullptr, nullptr, C, smh);
    }
}

// ---------------------------------------------------------------------------
// CSR build: fused count -> scans -> fused place (R16-validated)
// ---------------------------------------------------------------------------
__global__ void count2_kernel(const int* __restrict__ ce, const int* __restrict__ le,
                              int E, int* __restrict__ cntC, int* __restrict__ cntL)
{
    int e = blockIdx.x * 256 + threadIdx.x;
    if (e < E) {
        atomicAdd(&cntC[ce[e]], 1);
        atomicAdd(&cntL[le[e]], 1);
    }
}

__global__ void scan_reduce(const int* __restrict__ cnt, int n, int* __restrict__ bsum)
{
    int b = blockIdx.x;
    int CH = (n + SCAN_NB - 1) / SCAN_NB;
    int s = b * CH, e = min(n, s + CH);
    __shared__ int sh[256];
    int t = threadIdx.x, sum = 0;
    for (int i = s + t; i < e; i += 256) sum += cnt[i];
    sh[t] = sum; __syncthreads();
    for (int o = 128; o > 0; o >>= 1) {
        if (t < o) sh[t] += sh[t + o];
        __syncthreads();
    }
    if (t == 0) bsum[b] = sh[0];
}

__global__ void scan_bsum(int* __restrict__ bsum)
{
    __shared__ int sh[256];
    int t = threadIdx.x;
    sh[t] = bsum[t]; __syncthreads();
    for (int o = 1; o < 256; o <<= 1) {
        int v = (t >= o) ? sh[t - o] : 0;
        __syncthreads();
        sh[t] += v;
        __syncthreads();
    }
    bsum[t] = (t == 0) ? 0 : sh[t - 1];
}

__global__ void scan_write(const int* __restrict__ cnt, int n,
                           const int* __restrict__ bsum, int* __restrict__ rowptr, int total)
{
    int b = blockIdx.x;
    int CH = (n + SCAN_NB - 1) / SCAN_NB;
    int s = b * CH, e = min(n, s + CH);
    int t = threadIdx.x;
    int per = (CH + 255) / 256;
    int ts = min(e, s + t * per), te = min(e, s + t * per + per);
    int sum = 0;
    for (int i = ts; i < te; ++i) sum += cnt[i];
    __shared__ int sh[256];
    sh[t] = sum; __syncthreads();
    for (int o = 1; o < 256; o <<= 1) {
        int v = (t >= o) ? sh[t - o] : 0;
        __syncthreads();
        sh[t] += v;
        __syncthreads();
    }
    int off = bsum[b] + ((t == 0) ? 0 : sh[t - 1]);
    for (int i = ts; i < te; ++i) { rowptr[i] = off; off += cnt[i]; }
    if (b == 0 && t == 0) rowptr[n] = total;
}

__global__ void place2_kernel(const int* __restrict__ ce, const int* __restrict__ le,
                              int E, int* __restrict__ curC, int* __restrict__ srcC,
                              int* __restrict__ curL, int* __restrict__ srcL)
{
    int e = blockIdx.x * 256 + threadIdx.x;
    if (e < E) {
        int c = ce[e], l = le[e];
        srcC[atomicAdd(&curC[c], 1)] = l;
        srcL[atomicAdd(&curL[l], 1)] = c;
    }
}

// ---------------------------------------------------------------------------
// Merged gather: groups of 7 blocks = 5 L-gather + 2 C-gather (resident cost
// balanced: 5*80 vs 2*200 edge-loads). Body = R11-validated half-warp loop.
// ---------------------------------------------------------------------------
__device__ __forceinline__ void gather_body(
    const float* __restrict__ src, const int* __restrict__ srcidx,
    const int* __restrict__ rowptr, float* __restrict__ dst, int n, int vb)
{
    int d = vb * 16 + (threadIdx.x >> 4);
    int q = threadIdx.x & 15;
    if (d >= n) return;
    int s = rowptr[d], e = rowptr[d + 1];
    float ax = 0.f, ay = 0.f, az = 0.f, aw = 0.f;
    for (int i = s; i < e; ++i) {
        int r = __ldg(srcidx + i);
        float4 v = *(const float4*)(src + (size_t)r * 64 + q * 4);
        ax += v.x; ay += v.y; az += v.z; aw += v.w;
    }
    *(float4*)(dst + (size_t)d * 64 + q * 4) = make_float4(ax, ay, az, aw);
}

__global__ __launch_bounds__(256) void gather2_kernel(
    const float* __restrict__ srcL_m, const int* __restrict__ idxL,
    const int* __restrict__ rowL, float* __restrict__ aggrL, int nL,
    const float* __restrict__ srcC_m, const int* __restrict__ idxC,
    const int* __restrict__ rowC, float* __restrict__ aggrC, int nC)
{
    int g = blockIdx.x / 7, r = blockIdx.x - g * 7;
    if (r < 5) {
        int vb = g * 5 + r;
        if (vb * 16 < nL) gather_body(srcL_m, idxL, rowL, aggrL, nL, vb);
    } else {
        int vb = g * 2 + (r - 5);
        if (vb * 16 < nC) gather_body(srcC_m, idxC, rowC, aggrC, nC, vb);
    }
}

// ---------------------------------------------------------------------------
static inline size_t mlp_smem_bytes(int parts, bool fuse)
{
    size_t WS = parts * 64 + 8;
    size_t halves = 2 * 64 * WS + 2 * 64 * 72 + (fuse ? 4 * 64 * 72 : 0)
                  + (size_t)2 * 128 * 72;
    return halves * 2 + 256 * sizeof(float);
}

extern "C" void kernel_launch(void* const* d_in, const int* in_sizes, int n_in,
                              void* d_out, int out_size)
{
    const int off = n_in - 24;
    const int* l_edge = (const int*)d_in[off + 0];
    const int* c_edge = (const int*)d_in[off + 1];
    const float* l_emb_in = (const float*)d_in[off + 2];
    const float* c_emb_in = (const float*)d_in[off + 3];
    const int E = in_sizes[off + 0];
    const int L = in_sizes[off + 2] / DIM;
    const int C = in_sizes[off + 3] / DIM;

    const float* W[5][4];
    for (int m = 0; m < 5; ++m)
        for (int j = 0; j < 4; ++j)
            W[m][j] = (const float*)d_in[off + 4 + m * 4 + j];
    // m: 0=l2c, 1=c2l, 2=l2l, 3=cu, 4=lu

    float* Ml2c, * Mc2l, * Ml2l, * aggrC, * aggrL;
    int *cntC, *rowC, *curC, *srcC, *bsC;
    int *cntL, *rowL, *curL, *srcL, *bsL;
    cudaGetSymbolAddress((void**)&Ml2c, g_Ml2c);
    cudaGetSymbolAddress((void**)&Mc2l, g_Mc2l);
    cudaGetSymbolAddress((void**)&Ml2l, g_Ml2l);
    cudaGetSymbolAddress((void**)&aggrC, g_aggrC);
    cudaGetSymbolAddress((void**)&aggrL, g_aggrL);
    cudaGetSymbolAddress((void**)&cntC, g_cntC);
    cudaGetSymbolAddress((void**)&rowC, g_rowC);
    cudaGetSymbolAddress((void**)&curC, g_curC);
    cudaGetSymbolAddress((void**)&srcC, g_srcC);
    cudaGetSymbolAddress((void**)&bsC,  g_bsumC);
    cudaGetSymbolAddress((void**)&cntL, g_cntL);
    cudaGetSymbolAddress((void**)&rowL, g_rowL);
    cudaGetSymbolAddress((void**)&curL, g_curL);
    cudaGetSymbolAddress((void**)&srcL, g_srcL);
    cudaGetSymbolAddress((void**)&bsL,  g_bsumL);

    const size_t smF = mlp_smem_bytes(1, true);   // messages (largest path)
    const size_t smU = mlp_smem_bytes(3, false);  // updates  (largest path)
    cudaFuncSetAttribute(mlp_msg, cudaFuncAttributeMaxDynamicSharedMemorySize, (int)smF);
    cudaFuncSetAttribute(mlp_upd, cudaFuncAttributeMaxDynamicSharedMemorySize, (int)smU);

    float* outBase = (float*)d_out;
    float* outL = outBase;                          // (3, L, 64)
    float* outC = outBase + (size_t)3 * L * DIM;    // (3, C, 64)

    cudaMemcpyAsync(outL, l_emb_in, (size_t)L * DIM * sizeof(float), cudaMemcpyDeviceToDevice);
    cudaMemcpyAsync(outC, c_emb_in, (size_t)C * DIM * sizeof(float), cudaMemcpyDeviceToDevice);

    // ---- CSR build (fused per-edge passes) ----
    const int eb = (E + 255) / 256;
    cudaMemsetAsync(cntC, 0, C * sizeof(int));
    cudaMemsetAsync(cntL, 0, L * sizeof(int));
    count2_kernel<<<eb, 256>>>(c_edge, l_edge, E, cntC, cntL);
    scan_reduce<<<SCAN_NB, 256>>>(cntC, C, bsC);
    scan_reduce<<<SCAN_NB, 256>>>(cntL, L, bsL);
    scan_bsum<<<1, 256>>>(bsC);
    scan_bsum<<<1, 256>>>(bsL);
    scan_write<<<SCAN_NB, 256>>>(cntC, C, bsC, rowC, E);
    scan_write<<<SCAN_NB, 256>>>(cntL, L, bsL, rowL, E);
    cudaMemcpyAsync(curC, rowC, C * sizeof(int), cudaMemcpyDeviceToDevice);
    cudaMemcpyAsync(curL, rowL, L * sizeof(int), cudaMemcpyDeviceToDevice);
    place2_kernel<<<eb, 256>>>(c_edge, l_edge, E, curC, srcC, curL, srcL);

    const int gMsg = 294;  // divisible by 6 (5 fused-L : 1 c2l per group)
    const int gUpd = 296;  // divisible by 4 (3 lu : 1 cu per group)
    const int blocksL = (L / DIM + 15) / 16 + ((L % DIM) ? 1 : 0); // = ceil(L/16)/??  — see below
    const int nGL = (L + 15) / 16;
    const int nGC = (C + 15) / 16;
    const int gGather = ((nGL + 4) / 5 > (nGC + 1) / 2 ? (nGL + 4) / 5 : (nGC + 1) / 2) * 7;
    (void)blocksL;

    for (int t = 0; t < 2; ++t) {
        const float* le = outL + (size_t)t * L * DIM;
        const float* ce = outC + (size_t)t * C * DIM;
        float* nle = outL + (size_t)(t + 1) * L * DIM;
        float* nce = outC + (size_t)(t + 1) * C * DIM;

        // merged messages: fused l2c+l2l (L) || c2l (C)
        mlp_msg<<<gMsg, 256, smF>>>(le, ce,
            W[0][0], W[0][1], W[0][2], W[0][3],
            W[2][0], W[2][1], W[2][2], W[2][3],
            W[1][0], W[1][1], W[1][2], W[1][3],
            Ml2c, Ml2l, Mc2l, L, C);

        // merged gathers: aggrL (from Mc2l) || aggrC (from Ml2c)
        gather2_kernel<<<gGather, 256>>>(Mc2l, srcL, rowL, aggrL, L,
                                         Ml2c, srcC, rowC, aggrC, C);

        // merged updates: lu (L) || cu (C)
        mlp_upd<<<gUpd, 256, smU>>>(le, ce, aggrL, aggrC, Ml2l,
            W[4][0], W[4][1], W[4][2], W[4][3],
            W[3][0], W[3][1], W[3][2], W[3][3],
            nle, nce, L, C);
    }
    (void)out_size;
}